// round 6
// baseline (speedup 1.0000x reference)
#include <cuda_runtime.h>
#include <cuda_bf16.h>
#include <stdint.h>
#include <math.h>

#define NQ 4
#define DIM 16
#define KTOT 160

// ---------------- device globals ----------------
__device__ float g_M[2][DIM][DIM];                      // quadratic forms
// W-hi bf16 scratch, chunk-contiguous: [chunk(5, k32 each)][col 512][64B]
__device__ __align__(16) unsigned char g_Wc[5 * 32768];

// ---------------- helpers ----------------
static __device__ __forceinline__ uint32_t smem_u32(const void* p) {
    uint32_t a;
    asm("{ .reg .u64 t; cvta.to.shared.u64 t, %1; cvt.u32.u64 %0, t; }" : "=r"(a) : "l"(p));
    return a;
}
static __device__ __forceinline__ void cp_async16(uint32_t dst, const void* src) {
    asm volatile("cp.async.cg.shared.global [%0], [%1], 16;" :: "r"(dst), "l"(src) : "memory");
}
static __device__ __forceinline__ void ldsm4(uint32_t* r, uint32_t addr) {
    asm volatile("ldmatrix.sync.aligned.m8n8.x4.shared.b16 {%0,%1,%2,%3}, [%4];"
                 : "=r"(r[0]), "=r"(r[1]), "=r"(r[2]), "=r"(r[3]) : "r"(addr));
}
static __device__ __forceinline__ void mma16816(float* d, const uint32_t* a,
                                                uint32_t b0, uint32_t b1) {
    asm volatile("mma.sync.aligned.m16n8k16.row.col.f32.bf16.bf16.f32 "
                 "{%0,%1,%2,%3}, {%4,%5,%6,%7}, {%8,%9}, {%0,%1,%2,%3};"
                 : "+f"(d[0]), "+f"(d[1]), "+f"(d[2]), "+f"(d[3])
                 : "r"(a[0]), "r"(a[1]), "r"(a[2]), "r"(a[3]), "r"(b0), "r"(b1));
}

// ---------------------------------------------------------------------------
// Prep kernel (merged): blocks 0..159 convert W1->bf16-hi scratch;
// block 160 builds the quantum quadratic forms.
// ---------------------------------------------------------------------------
__global__ void qc_prep_kernel(const float* __restrict__ W11, const float* __restrict__ W12,
                               const float* __restrict__ qw1, const float* __restrict__ qw2,
                               const float* __restrict__ pw1, const float* __restrict__ pw2) {
    if (blockIdx.x < 160) {
        int id = blockIdx.x * 512 + threadIdx.x;   // 81920 = 512 cols * 160 k
        int col = id >> 7;          // id / 160? no: use div
        col = id / 160;
        int k = id - col * 160;
        const float* W = (col < 256) ? W11 : W12;
        float w = W[(col & 255) * KTOT + k];
        __nv_bfloat16 hi = __float2bfloat16_rn(w);
        // chunk-contiguous global layout: [k/32][col][k%32]
        uint32_t off = (uint32_t)(k >> 5) * 32768 + (uint32_t)col * 64 + (uint32_t)(k & 31) * 2;
        *(unsigned short*)(g_Wc + off) = __bfloat16_as_ushort(hi);
        return;
    }
    // ---- quantum setup (block 160, threads 0..31) ----
    __shared__ float sUr[2][DIM][DIM];
    __shared__ float sUi[2][DIM][DIM];
    int t = threadIdx.x;
    if (t < 32) {
        int br  = t >> 4;
        int col = t & 15;
        const float* qw = br ? qw2 : qw1;
        float vr[DIM], vi[DIM];
        #pragma unroll
        for (int k = 0; k < DIM; k++) { vr[k] = (k == col) ? 1.f : 0.f; vi[k] = 0.f; }

        for (int l = 0; l < 2; l++) {
            for (int q = 0; q < NQ; q++) {
                int s = 8 >> q;
                {   // RX
                    float th = qw[(l * NQ + q) * 3 + 0];
                    float c, sn; sincosf(0.5f * th, &sn, &c);
                    #pragma unroll
                    for (int i0 = 0; i0 < DIM; i0++) if (!(i0 & s)) {
                        int i1 = i0 | s;
                        float ar = vr[i0], ai = vi[i0], b_r = vr[i1], b_i = vi[i1];
                        vr[i0] = c * ar + sn * b_i;  vi[i0] = c * ai - sn * b_r;
                        vr[i1] = c * b_r + sn * ai;  vi[i1] = c * b_i - sn * ar;
                    }
                }
                {   // RY
                    float th = qw[(l * NQ + q) * 3 + 1];
                    float c, sn; sincosf(0.5f * th, &sn, &c);
                    #pragma unroll
                    for (int i0 = 0; i0 < DIM; i0++) if (!(i0 & s)) {
                        int i1 = i0 | s;
                        float ar = vr[i0], ai = vi[i0], b_r = vr[i1], b_i = vi[i1];
                        vr[i0] = c * ar - sn * b_r;  vi[i0] = c * ai - sn * b_i;
                        vr[i1] = sn * ar + c * b_r;  vi[i1] = sn * ai + c * b_i;
                    }
                }
                {   // RZ
                    float th = qw[(l * NQ + q) * 3 + 2];
                    float c, sn; sincosf(0.5f * th, &sn, &c);
                    #pragma unroll
                    for (int i0 = 0; i0 < DIM; i0++) {
                        float ar = vr[i0], ai = vi[i0];
                        if (i0 & s) { vr[i0] = c * ar - sn * ai; vi[i0] = c * ai + sn * ar; }
                        else        { vr[i0] = c * ar + sn * ai; vi[i0] = c * ai - sn * ar; }
                    }
                }
            }
            const int scs[4] = {8, 4, 2, 1};
            const int sts[4] = {4, 2, 1, 8};
            #pragma unroll
            for (int p = 0; p < 4; p++) {
                int sc = scs[p], st = sts[p];
                #pragma unroll
                for (int i0 = 0; i0 < DIM; i0++)
                    if ((i0 & sc) && !(i0 & st)) {
                        int i1 = i0 | st;
                        float tr = vr[i0], ti = vi[i0];
                        vr[i0] = vr[i1]; vi[i0] = vi[i1];
                        vr[i1] = tr;     vi[i1] = ti;
                    }
            }
        }
        #pragma unroll
        for (int k = 0; k < DIM; k++) { sUr[br][k][col] = vr[k]; sUi[br][k][col] = vi[k]; }
    }
    __syncthreads();
    if (t < 32) {
        int br = t >> 4;
        int i  = t & 15;
        float pw = br ? pw2[0] : pw1[0];
        for (int j = 0; j < DIM; j++) {
            float acc = 0.f;
            #pragma unroll
            for (int k = 0; k < DIM; k++) {
                float d = (k < 8) ? 1.f : -1.f;
                acc += d * (sUr[br][k][i] * sUr[br][k][j] + sUi[br][k][i] * sUi[br][k][j]);
            }
            g_M[br][i][j] = acc * pw;
        }
    }
}

// ---------------------------------------------------------------------------
// Main HMMA kernel. CTA: 512 thr = 16 warps (wm = wid&1, wn = wid>>1).
// Tile M=64 x N=512. h = (xh + xl) * wh : xl MMAs accumulate into the same
// accumulators, reusing B fragments.
// smem map:
//   [0, 41984)          X tile: 64 rows x pitch 656B (xh @0..319, xl @320..639)
//   [41984, 214016)     W: 512 cols x pitch 336B (k 0..159 bf16, linear)
// epilogue overlay (X region): ps @0 (8KB), sW2 @8192 (8KB), sB1 @16384 (2KB)
// ---------------------------------------------------------------------------
#define XOFF  0u
#define WOFF  41984u
#define WPITCH 336u
#define SMEM_BYTES 214016

__global__ __launch_bounds__(512, 1)
void qc_hmma_kernel(const float* __restrict__ state, const float* __restrict__ action,
                    const float* __restrict__ b11, const float* __restrict__ b12,
                    const float* __restrict__ W21, const float* __restrict__ W22,
                    const float* __restrict__ b21, const float* __restrict__ b22,
                    const float* __restrict__ pb1, const float* __restrict__ pb2,
                    float* __restrict__ out, int B) {
    extern __shared__ char smem[];
    uint32_t sb = smem_u32(smem);
    int t = threadIdx.x, lane = t & 31, wid = t >> 5;
    int wm = wid & 1, wn = wid >> 1;
    int row0 = blockIdx.x * 64;

    // issue all W loads up front, 5 commit groups (k32 each, coalesced src)
    #pragma unroll
    for (int c = 0; c < 5; c++) {
        const unsigned char* src = g_Wc + (size_t)c * 32768;
        #pragma unroll
        for (int i = 0; i < 4; i++) {
            // dst: col-pitch layout; col = t, bytes [c*64 + i*16)
            cp_async16(sb + WOFF + (uint32_t)t * WPITCH + (uint32_t)(c * 64 + i * 16),
                       src + t * 64 + i * 16);
        }
        asm volatile("cp.async.commit_group;" ::: "memory");
    }

    // X tile: load fp32, split to hi/lo bf16, store to smem
    #pragma unroll
    for (int p = 0; p < 3; p++) {
        int task = t + p * 512;
        if (task < 1280) {
            int r = task / 20, g = task - r * 20;
            const float* src = (g < 16) ? state + (size_t)(row0 + r) * 128 + g * 8
                                        : action + (size_t)(row0 + r) * 32 + (g - 16) * 8;
            float4 va = *(const float4*)src;
            float4 vb = *(const float4*)(src + 4);
            float v[8] = {va.x, va.y, va.z, va.w, vb.x, vb.y, vb.z, vb.w};
            uint32_t hp[4], lp[4];
            #pragma unroll
            for (int i = 0; i < 4; i++) {
                __nv_bfloat16 h0 = __float2bfloat16_rn(v[2 * i]);
                __nv_bfloat16 h1 = __float2bfloat16_rn(v[2 * i + 1]);
                __nv_bfloat16 l0 = __float2bfloat16_rn(v[2 * i] - __bfloat162float(h0));
                __nv_bfloat16 l1 = __float2bfloat16_rn(v[2 * i + 1] - __bfloat162float(h1));
                hp[i] = (uint32_t)__bfloat16_as_ushort(h0) | ((uint32_t)__bfloat16_as_ushort(h1) << 16);
                lp[i] = (uint32_t)__bfloat16_as_ushort(l0) | ((uint32_t)__bfloat16_as_ushort(l1) << 16);
            }
            uint32_t base = sb + XOFF + (uint32_t)(r * 656 + g * 16);
            asm volatile("st.shared.v4.b32 [%0], {%1,%2,%3,%4};"
                         :: "r"(base), "r"(hp[0]), "r"(hp[1]), "r"(hp[2]), "r"(hp[3]) : "memory");
            asm volatile("st.shared.v4.b32 [%0], {%1,%2,%3,%4};"
                         :: "r"(base + 320), "r"(lp[0]), "r"(lp[1]), "r"(lp[2]), "r"(lp[3]) : "memory");
        }
    }

    // per-lane ldmatrix bases
    uint32_t a_base = sb + XOFF + (uint32_t)((wm * 32 + (lane & 15)) * 656 + (lane >> 4) * 16);
    uint32_t b_base = sb + WOFF + (uint32_t)((wn * 64 + (lane & 15)) * WPITCH + (lane >> 4) * 16);

    float acc[2][8][4];
    #pragma unroll
    for (int m = 0; m < 2; m++)
        #pragma unroll
        for (int n = 0; n < 8; n++)
            #pragma unroll
            for (int j = 0; j < 4; j++) acc[m][n][j] = 0.f;

    #pragma unroll 1
    for (int kb = 0; kb < 10; kb++) {
        if ((kb & 1) == 0) {
            // W chunk kb/2 must be resident (groups committed in order 0..4)
            switch (kb >> 1) {
                case 0: asm volatile("cp.async.wait_group 4;" ::: "memory"); break;
                case 1: asm volatile("cp.async.wait_group 3;" ::: "memory"); break;
                case 2: asm volatile("cp.async.wait_group 2;" ::: "memory"); break;
                case 3: asm volatile("cp.async.wait_group 1;" ::: "memory"); break;
                default: asm volatile("cp.async.wait_group 0;" ::: "memory"); break;
            }
            __syncthreads();
        }
        uint32_t koff = (uint32_t)(kb * 32);
        uint32_t ah[4], al[4];
        ldsm4(ah, a_base + koff);            // xh rows m0..15 (of warp tile)
        ldsm4(al, a_base + 320 + koff);      // xl same rows
        uint32_t ah2[4], al2[4];
        ldsm4(ah2, a_base + 16 * 656 + koff);
        ldsm4(al2, a_base + 16 * 656 + 320 + koff);
        #pragma unroll
        for (int n2 = 0; n2 < 4; n2++) {
            uint32_t bfr[4];
            ldsm4(bfr, b_base + (uint32_t)(n2 * 16) * WPITCH + koff);
            mma16816(acc[0][2 * n2],     ah,  bfr[0], bfr[2]);
            mma16816(acc[0][2 * n2 + 1], ah,  bfr[1], bfr[3]);
            mma16816(acc[1][2 * n2],     ah2, bfr[0], bfr[2]);
            mma16816(acc[1][2 * n2 + 1], ah2, bfr[1], bfr[3]);
            mma16816(acc[0][2 * n2],     al,  bfr[0], bfr[2]);
            mma16816(acc[0][2 * n2 + 1], al,  bfr[1], bfr[3]);
            mma16816(acc[1][2 * n2],     al2, bfr[0], bfr[2]);
            mma16816(acc[1][2 * n2 + 1], al2, bfr[1], bfr[3]);
        }
    }

    // ---------------- epilogue ----------------
    __syncthreads();   // mainloop done chip-wide in CTA; safe to overwrite X region
    float* ps  = (float*)(smem + 0);        // [8][64][4]
    float* sW2 = (float*)(smem + 8192);     // [512][4]
    float* sB1 = (float*)(smem + 16384);    // [512]
    {
        int col = t, cb = col & 255;
        const float* W2 = (col < 256) ? W21 : W22;
        sW2[col * 4 + 0] = W2[0 * 256 + cb];
        sW2[col * 4 + 1] = W2[1 * 256 + cb];
        sW2[col * 4 + 2] = W2[2 * 256 + cb];
        sW2[col * 4 + 3] = W2[3 * 256 + cb];
        sB1[col] = (col < 256) ? b11[col] : b12[cb];
    }
    __syncthreads();

    float p[4][4];
    #pragma unroll
    for (int s = 0; s < 4; s++)
        #pragma unroll
        for (int j = 0; j < 4; j++) p[s][j] = 0.f;

    #pragma unroll
    for (int m = 0; m < 2; m++)
        #pragma unroll
        for (int n = 0; n < 8; n++) {
            int c0 = wn * 64 + n * 8 + 2 * (lane & 3);
            float bb0 = sB1[c0], bb1 = sB1[c0 + 1];
            float h0 = fmaxf(acc[m][n][0] + bb0, 0.f);
            float h1 = fmaxf(acc[m][n][1] + bb1, 0.f);
            float h2 = fmaxf(acc[m][n][2] + bb0, 0.f);
            float h3 = fmaxf(acc[m][n][3] + bb1, 0.f);
            const float4 w0 = *(const float4*)(sW2 + c0 * 4);
            const float4 w1 = *(const float4*)(sW2 + (c0 + 1) * 4);
            p[2*m][0] = fmaf(w0.x, h0, fmaf(w1.x, h1, p[2*m][0]));
            p[2*m][1] = fmaf(w0.y, h0, fmaf(w1.y, h1, p[2*m][1]));
            p[2*m][2] = fmaf(w0.z, h0, fmaf(w1.z, h1, p[2*m][2]));
            p[2*m][3] = fmaf(w0.w, h0, fmaf(w1.w, h1, p[2*m][3]));
            p[2*m+1][0] = fmaf(w0.x, h2, fmaf(w1.x, h3, p[2*m+1][0]));
            p[2*m+1][1] = fmaf(w0.y, h2, fmaf(w1.y, h3, p[2*m+1][1]));
            p[2*m+1][2] = fmaf(w0.z, h2, fmaf(w1.z, h3, p[2*m+1][2]));
            p[2*m+1][3] = fmaf(w0.w, h2, fmaf(w1.w, h3, p[2*m+1][3]));
        }
    #pragma unroll
    for (int off = 1; off < 4; off <<= 1)
        #pragma unroll
        for (int s = 0; s < 4; s++)
            #pragma unroll
            for (int j = 0; j < 4; j++)
                p[s][j] += __shfl_xor_sync(0xffffffffu, p[s][j], off);

    if ((lane & 3) == 0) {
        int rq = lane >> 2;
        #pragma unroll
        for (int s = 0; s < 4; s++) {
            int row = wm * 32 + (s >> 1) * 16 + (s & 1) * 8 + rq;
            *(float4*)(ps + ((size_t)wn * 64 + row) * 4) =
                make_float4(p[s][0], p[s][1], p[s][2], p[s][3]);
        }
    }
    __syncthreads();

    if (t < 128) {
        int brx = t >> 6, row = t & 63;
        const float4* psv = (const float4*)ps;
        float4 s0 = psv[(4 * brx + 0) * 64 + row];
        float4 s1 = psv[(4 * brx + 1) * 64 + row];
        float4 s2 = psv[(4 * brx + 2) * 64 + row];
        float4 s3 = psv[(4 * brx + 3) * 64 + row];
        const float* b2 = brx ? b22 : b21;
        float q0 = s0.x + s1.x + s2.x + s3.x + __ldg(b2 + 0);
        float q1 = s0.y + s1.y + s2.y + s3.y + __ldg(b2 + 1);
        float q2 = s0.z + s1.z + s2.z + s3.z + __ldg(b2 + 2);
        float q3 = s0.w + s1.w + s2.w + s3.w + __ldg(b2 + 3);

        float cc4[4], ss4[4];
        sincosf(0.5f * q0, &ss4[0], &cc4[0]);
        sincosf(0.5f * q1, &ss4[1], &cc4[1]);
        sincosf(0.5f * q2, &ss4[2], &cc4[2]);
        sincosf(0.5f * q3, &ss4[3], &cc4[3]);
        float a[16];
        #pragma unroll
        for (int idx = 0; idx < 16; idx++) {
            float v = ((idx >> 3) & 1) ? ss4[0] : cc4[0];
            v *= ((idx >> 2) & 1) ? ss4[1] : cc4[1];
            v *= ((idx >> 1) & 1) ? ss4[2] : cc4[2];
            v *= (idx & 1) ? ss4[3] : cc4[3];
            a[idx] = v;
        }
        const float* M = &g_M[brx][0][0];
        float qo = 0.f;
        #pragma unroll
        for (int i2 = 0; i2 < 16; i2++) {
            float mi = 0.f;
            #pragma unroll
            for (int j = 0; j < 16; j++) mi = fmaf(M[i2 * 16 + j], a[j], mi);
            qo = fmaf(a[i2], mi, qo);
        }
        out[(size_t)brx * B + row0 + row] = qo + (brx ? __ldg(pb2) : __ldg(pb1));
    }
}

// ---------------------------------------------------------------------------
// Launch
// ---------------------------------------------------------------------------
extern "C" void kernel_launch(void* const* d_in, const int* in_sizes, int n_in,
                              void* d_out, int out_size) {
    const float* state  = (const float*)d_in[0];
    const float* action = (const float*)d_in[1];
    const float* q1_W1  = (const float*)d_in[2];
    const float* q1_b1  = (const float*)d_in[3];
    const float* q1_W2  = (const float*)d_in[4];
    const float* q1_b2  = (const float*)d_in[5];
    const float* q2_W1  = (const float*)d_in[6];
    const float* q2_b1  = (const float*)d_in[7];
    const float* q2_W2  = (const float*)d_in[8];
    const float* q2_b2  = (const float*)d_in[9];
    const float* q1_qw  = (const float*)d_in[10];
    const float* q2_qw  = (const float*)d_in[11];
    const float* q1_pw  = (const float*)d_in[12];
    const float* q1_pb  = (const float*)d_in[13];
    const float* q2_pw  = (const float*)d_in[14];
    const float* q2_pb  = (const float*)d_in[15];
    float* out = (float*)d_out;

    int B = in_sizes[0] / 128;

    cudaFuncSetAttribute(qc_hmma_kernel,
                         cudaFuncAttributeMaxDynamicSharedMemorySize, SMEM_BYTES);

    qc_prep_kernel<<<161, 512>>>(q1_W1, q2_W1, q1_qw, q2_qw, q1_pw, q2_pw);
    qc_hmma_kernel<<<B / 64, 512, SMEM_BYTES>>>(
        state, action, q1_b1, q2_b1, q1_W2, q2_W2, q1_b2, q2_b2,
        q1_pb, q2_pb, out, B);
}

// round 7
// speedup vs baseline: 1.3356x; 1.3356x over previous
#include <cuda_runtime.h>
#include <cuda_bf16.h>
#include <stdint.h>
#include <math.h>

#define NQ 4
#define DIM 16
#define KTOT 160

// ---------------- device globals ----------------
__device__ float g_M[2][DIM][DIM];                        // quadratic forms
__device__ __align__(16) unsigned char g_Wc[5 * 65536];   // W' bf16 [chunk][col 512][128B swizzled]

// ---------------- helpers ----------------
static __device__ __forceinline__ uint32_t smem_u32(const void* p) {
    uint32_t a;
    asm("{ .reg .u64 t; cvta.to.shared.u64 t, %1; cvt.u32.u64 %0, t; }" : "=r"(a) : "l"(p));
    return a;
}
static __device__ __forceinline__ void cp_async16(uint32_t dst, const void* src) {
    asm volatile("cp.async.cg.shared.global [%0], [%1], 16;" :: "r"(dst), "l"(src) : "memory");
}
static __device__ __forceinline__ void ldsm4(uint32_t* r, uint32_t addr) {
    asm volatile("ldmatrix.sync.aligned.m8n8.x4.shared.b16 {%0,%1,%2,%3}, [%4];"
                 : "=r"(r[0]), "=r"(r[1]), "=r"(r[2]), "=r"(r[3]) : "r"(addr));
}
static __device__ __forceinline__ void mma16816(float* d, const uint32_t* a,
                                                uint32_t b0, uint32_t b1) {
    asm volatile("mma.sync.aligned.m16n8k16.row.col.f32.bf16.bf16.f32 "
                 "{%0,%1,%2,%3}, {%4,%5,%6,%7}, {%8,%9}, {%0,%1,%2,%3};"
                 : "+f"(d[0]), "+f"(d[1]), "+f"(d[2]), "+f"(d[3])
                 : "r"(a[0]), "r"(a[1]), "r"(a[2]), "r"(a[3]), "r"(b0), "r"(b1));
}

// ---------------------------------------------------------------------------
// Prep kernel: blocks 0..319 build W scratch (bf16-hi duplicated in both K'
// halves so that A'=[xh|xl] times B'=[wh|wh] == (xh+xl)*wh); block 320 builds
// the quantum quadratic forms.
// W' layout (same as R4): chunk = k'/64; within col's row, group (k'%64)/8 at
// position ((kg ^ (col&7))*8 + k'%8)*2  -- conflict-free ldmatrix via XOR.
// ---------------------------------------------------------------------------
__global__ void qc_prep_kernel(const float* __restrict__ W11, const float* __restrict__ W12,
                               const float* __restrict__ qw1, const float* __restrict__ qw2,
                               const float* __restrict__ pw1, const float* __restrict__ pw2) {
    if (blockIdx.x < 320) {
        int id = blockIdx.x * 512 + threadIdx.x;   // 163840 = 512 cols * 320 k'
        int col = id / 320;
        int kp  = id - col * 320;
        const float* W = (col < 256) ? W11 : W12;
        int k = (kp < 160) ? kp : kp - 160;
        float w = W[(col & 255) * KTOT + k];
        __nv_bfloat16 val = __float2bfloat16_rn(w);    // hi in BOTH halves
        int chunk = kp >> 6, kin = kp & 63, kg = kin >> 3, ki = kin & 7;
        uint32_t off = (uint32_t)chunk * 65536 + (uint32_t)col * 128
                     + (uint32_t)(((kg ^ (col & 7)) * 8 + ki) * 2);
        *(unsigned short*)(g_Wc + off) = __bfloat16_as_ushort(val);
        return;
    }
    // ---- quantum setup (block 320, threads 0..31) ----
    __shared__ float sUr[2][DIM][DIM];
    __shared__ float sUi[2][DIM][DIM];
    int t = threadIdx.x;
    if (t < 32) {
        int br  = t >> 4;
        int col = t & 15;
        const float* qw = br ? qw2 : qw1;
        float vr[DIM], vi[DIM];
        #pragma unroll
        for (int k = 0; k < DIM; k++) { vr[k] = (k == col) ? 1.f : 0.f; vi[k] = 0.f; }

        for (int l = 0; l < 2; l++) {
            for (int q = 0; q < NQ; q++) {
                int s = 8 >> q;
                {   // RX
                    float th = qw[(l * NQ + q) * 3 + 0];
                    float c, sn; sincosf(0.5f * th, &sn, &c);
                    #pragma unroll
                    for (int i0 = 0; i0 < DIM; i0++) if (!(i0 & s)) {
                        int i1 = i0 | s;
                        float ar = vr[i0], ai = vi[i0], b_r = vr[i1], b_i = vi[i1];
                        vr[i0] = c * ar + sn * b_i;  vi[i0] = c * ai - sn * b_r;
                        vr[i1] = c * b_r + sn * ai;  vi[i1] = c * b_i - sn * ar;
                    }
                }
                {   // RY
                    float th = qw[(l * NQ + q) * 3 + 1];
                    float c, sn; sincosf(0.5f * th, &sn, &c);
                    #pragma unroll
                    for (int i0 = 0; i0 < DIM; i0++) if (!(i0 & s)) {
                        int i1 = i0 | s;
                        float ar = vr[i0], ai = vi[i0], b_r = vr[i1], b_i = vi[i1];
                        vr[i0] = c * ar - sn * b_r;  vi[i0] = c * ai - sn * b_i;
                        vr[i1] = sn * ar + c * b_r;  vi[i1] = sn * ai + c * b_i;
                    }
                }
                {   // RZ
                    float th = qw[(l * NQ + q) * 3 + 2];
                    float c, sn; sincosf(0.5f * th, &sn, &c);
                    #pragma unroll
                    for (int i0 = 0; i0 < DIM; i0++) {
                        float ar = vr[i0], ai = vi[i0];
                        if (i0 & s) { vr[i0] = c * ar - sn * ai; vi[i0] = c * ai + sn * ar; }
                        else        { vr[i0] = c * ar + sn * ai; vi[i0] = c * ai - sn * ar; }
                    }
                }
            }
            const int scs[4] = {8, 4, 2, 1};
            const int sts[4] = {4, 2, 1, 8};
            #pragma unroll
            for (int p = 0; p < 4; p++) {
                int sc = scs[p], st = sts[p];
                #pragma unroll
                for (int i0 = 0; i0 < DIM; i0++)
                    if ((i0 & sc) && !(i0 & st)) {
                        int i1 = i0 | st;
                        float tr = vr[i0], ti = vi[i0];
                        vr[i0] = vr[i1]; vi[i0] = vi[i1];
                        vr[i1] = tr;     vi[i1] = ti;
                    }
            }
        }
        #pragma unroll
        for (int k = 0; k < DIM; k++) { sUr[br][k][col] = vr[k]; sUi[br][k][col] = vi[k]; }
    }
    __syncthreads();
    if (t < 32) {
        int br = t >> 4;
        int i  = t & 15;
        float pw = br ? pw2[0] : pw1[0];
        for (int j = 0; j < DIM; j++) {
            float acc = 0.f;
            #pragma unroll
            for (int k = 0; k < DIM; k++) {
                float d = (k < 8) ? 1.f : -1.f;
                acc += d * (sUr[br][k][i] * sUr[br][k][j] + sUi[br][k][i] * sUi[br][k][j]);
            }
            g_M[br][i][j] = acc * pw;
        }
    }
}

// ---------------------------------------------------------------------------
// Main HMMA kernel (R4 structure). CTA: 512 thr = 16 warps (wm=wid&1, wn=wid>>1).
// Tile M=64 x N=512, K'=320 in five 64-k chunks, double-buffered cp.async.
// smem map (bytes):
//   [0, 41984)        X tile: 64 rows x 328 bf16 (pitch 656B), cols 0..319 used
//   [41984, 173056)   W double buffer: 2 x 512 cols x 128B (swizzled)
//   [173056, 181248)  ps[8][64][4] f32 partial qin
//   [181248, 189440)  sW2[512][4] f32
//   [189440, 191488)  sB1[512] f32
// ---------------------------------------------------------------------------
#define XOFF  0u
#define WOFF  41984u
#define PSOFF 173056u
#define W2OFF 181248u
#define B1OFF 189440u
#define SMEM_BYTES 191488

__global__ __launch_bounds__(512, 1)
void qc_hmma_kernel(const float* __restrict__ state, const float* __restrict__ action,
                    const float* __restrict__ b11, const float* __restrict__ b12,
                    const float* __restrict__ W21, const float* __restrict__ W22,
                    const float* __restrict__ b21, const float* __restrict__ b22,
                    const float* __restrict__ pb1, const float* __restrict__ pb2,
                    float* __restrict__ out, int B) {
    extern __shared__ char smem[];
    uint32_t sb = smem_u32(smem);
    int t = threadIdx.x, lane = t & 31, wid = t >> 5;
    int wm = wid & 1, wn = wid >> 1;
    int row0 = blockIdx.x * 64;

    // prefetch W chunk 0 (fully coalesced: contiguous 16B per lane)
    #pragma unroll
    for (int i = 0; i < 8; i++)
        cp_async16(sb + WOFF + (uint32_t)(t * 16 + i * 8192), g_Wc + t * 16 + i * 8192);
    asm volatile("cp.async.commit_group;" ::: "memory");

    // X tile: load fp32, split to hi/lo bf16, store to smem
    #pragma unroll
    for (int p = 0; p < 3; p++) {
        int task = t + p * 512;
        if (task < 1280) {
            int r = task / 20, g = task - r * 20;
            const float* src = (g < 16) ? state + (size_t)(row0 + r) * 128 + g * 8
                                        : action + (size_t)(row0 + r) * 32 + (g - 16) * 8;
            float4 va = *(const float4*)src;
            float4 vb = *(const float4*)(src + 4);
            float v[8] = {va.x, va.y, va.z, va.w, vb.x, vb.y, vb.z, vb.w};
            uint32_t hp[4], lp[4];
            #pragma unroll
            for (int i = 0; i < 4; i++) {
                __nv_bfloat16 h0 = __float2bfloat16_rn(v[2 * i]);
                __nv_bfloat16 h1 = __float2bfloat16_rn(v[2 * i + 1]);
                __nv_bfloat16 l0 = __float2bfloat16_rn(v[2 * i] - __bfloat162float(h0));
                __nv_bfloat16 l1 = __float2bfloat16_rn(v[2 * i + 1] - __bfloat162float(h1));
                hp[i] = (uint32_t)__bfloat16_as_ushort(h0) | ((uint32_t)__bfloat16_as_ushort(h1) << 16);
                lp[i] = (uint32_t)__bfloat16_as_ushort(l0) | ((uint32_t)__bfloat16_as_ushort(l1) << 16);
            }
            uint32_t base = sb + XOFF + (uint32_t)(r * 656 + g * 16);
            asm volatile("st.shared.v4.b32 [%0], {%1,%2,%3,%4};"
                         :: "r"(base), "r"(hp[0]), "r"(hp[1]), "r"(hp[2]), "r"(hp[3]) : "memory");
            asm volatile("st.shared.v4.b32 [%0], {%1,%2,%3,%4};"
                         :: "r"(base + 320), "r"(lp[0]), "r"(lp[1]), "r"(lp[2]), "r"(lp[3]) : "memory");
        }
    }
    // stage sW2 and sB1
    {
        int col = t, cb = col & 255;
        const float* W2 = (col < 256) ? W21 : W22;
        float4 w4 = make_float4(W2[0 * 256 + cb], W2[1 * 256 + cb],
                                W2[2 * 256 + cb], W2[3 * 256 + cb]);
        *(float4*)(smem + W2OFF + (size_t)col * 16) = w4;
        ((float*)(smem + B1OFF))[col] = (col < 256) ? b11[col] : b12[cb];
    }

    // per-lane ldmatrix bases
    uint32_t a_base = sb + XOFF + (uint32_t)((wm * 32 + (lane & 15)) * 656 + (lane >> 4) * 16);
    uint32_t b_base = (uint32_t)((wn * 64 + (lane & 15)) * 128);
    uint32_t ssx = lane & 7, hh = lane >> 4;

    float acc[2][8][4];
    #pragma unroll
    for (int m = 0; m < 2; m++)
        #pragma unroll
        for (int n = 0; n < 8; n++)
            #pragma unroll
            for (int j = 0; j < 4; j++) acc[m][n][j] = 0.f;

    #pragma unroll 1
    for (int c = 0; c < 5; c++) {
        asm volatile("cp.async.wait_group 0;" ::: "memory");
        __syncthreads();
        if (c < 4) {   // prefetch next chunk into other buffer (read done last iter)
            const unsigned char* src = g_Wc + (size_t)(c + 1) * 65536;
            uint32_t dst = sb + WOFF + (uint32_t)(((c + 1) & 1) * 65536);
            #pragma unroll
            for (int i = 0; i < 8; i++)
                cp_async16(dst + (uint32_t)(t * 16 + i * 8192), src + t * 16 + i * 8192);
            asm volatile("cp.async.commit_group;" ::: "memory");
        }
        uint32_t wbuf = sb + WOFF + (uint32_t)((c & 1) * 65536);
        #pragma unroll
        for (int ks = 0; ks < 4; ks++) {
            uint32_t a0[4], a1[4];
            uint32_t koff = (uint32_t)((c * 64 + ks * 16) * 2);
            ldsm4(a0, a_base + koff);
            ldsm4(a1, a_base + 16 * 656 + koff);
            uint32_t kgx = (((uint32_t)(ks * 2) + hh) ^ ssx) << 4;
            #pragma unroll
            for (int n2 = 0; n2 < 4; n2++) {
                uint32_t bfr[4];
                ldsm4(bfr, wbuf + b_base + (uint32_t)(n2 * 2048) + kgx);
                mma16816(acc[0][2 * n2],     a0, bfr[0], bfr[2]);
                mma16816(acc[0][2 * n2 + 1], a0, bfr[1], bfr[3]);
                mma16816(acc[1][2 * n2],     a1, bfr[0], bfr[2]);
                mma16816(acc[1][2 * n2 + 1], a1, bfr[1], bfr[3]);
            }
        }
    }

    // ---------------- epilogue: bias + relu + W2 contraction ----------------
    const float* sB1 = (const float*)(smem + B1OFF);
    const float4* sW2 = (const float4*)(smem + W2OFF);
    float p[4][4];
    #pragma unroll
    for (int s = 0; s < 4; s++)
        #pragma unroll
        for (int j = 0; j < 4; j++) p[s][j] = 0.f;

    #pragma unroll
    for (int m = 0; m < 2; m++)
        #pragma unroll
        for (int n = 0; n < 8; n++) {
            int c0 = wn * 64 + n * 8 + 2 * (lane & 3);
            float bb0 = sB1[c0], bb1 = sB1[c0 + 1];
            float h0 = fmaxf(acc[m][n][0] + bb0, 0.f);
            float h1 = fmaxf(acc[m][n][1] + bb1, 0.f);
            float h2 = fmaxf(acc[m][n][2] + bb0, 0.f);
            float h3 = fmaxf(acc[m][n][3] + bb1, 0.f);
            float4 w0 = sW2[c0], w1 = sW2[c0 + 1];
            p[2*m][0] = fmaf(w0.x, h0, fmaf(w1.x, h1, p[2*m][0]));
            p[2*m][1] = fmaf(w0.y, h0, fmaf(w1.y, h1, p[2*m][1]));
            p[2*m][2] = fmaf(w0.z, h0, fmaf(w1.z, h1, p[2*m][2]));
            p[2*m][3] = fmaf(w0.w, h0, fmaf(w1.w, h1, p[2*m][3]));
            p[2*m+1][0] = fmaf(w0.x, h2, fmaf(w1.x, h3, p[2*m+1][0]));
            p[2*m+1][1] = fmaf(w0.y, h2, fmaf(w1.y, h3, p[2*m+1][1]));
            p[2*m+1][2] = fmaf(w0.z, h2, fmaf(w1.z, h3, p[2*m+1][2]));
            p[2*m+1][3] = fmaf(w0.w, h2, fmaf(w1.w, h3, p[2*m+1][3]));
        }
    #pragma unroll
    for (int off = 1; off < 4; off <<= 1)
        #pragma unroll
        for (int s = 0; s < 4; s++)
            #pragma unroll
            for (int j = 0; j < 4; j++)
                p[s][j] += __shfl_xor_sync(0xffffffffu, p[s][j], off);

    if ((lane & 3) == 0) {
        int rq = lane >> 2;
        #pragma unroll
        for (int s = 0; s < 4; s++) {
            int row = wm * 32 + (s >> 1) * 16 + (s & 1) * 8 + rq;
            *(float4*)(smem + PSOFF + (size_t)(wn * 64 + row) * 16) =
                make_float4(p[s][0], p[s][1], p[s][2], p[s][3]);
        }
    }
    __syncthreads();

    if (t < 128) {
        int brx = t >> 6, row = t & 63;
        const float4* ps = (const float4*)(smem + PSOFF);
        float4 s0 = ps[(4 * brx + 0) * 64 + row];
        float4 s1 = ps[(4 * brx + 1) * 64 + row];
        float4 s2 = ps[(4 * brx + 2) * 64 + row];
        float4 s3 = ps[(4 * brx + 3) * 64 + row];
        const float* b2 = brx ? b22 : b21;
        float q0 = s0.x + s1.x + s2.x + s3.x + __ldg(b2 + 0);
        float q1 = s0.y + s1.y + s2.y + s3.y + __ldg(b2 + 1);
        float q2 = s0.z + s1.z + s2.z + s3.z + __ldg(b2 + 2);
        float q3 = s0.w + s1.w + s2.w + s3.w + __ldg(b2 + 3);

        float cc4[4], ss4[4];
        sincosf(0.5f * q0, &ss4[0], &cc4[0]);
        sincosf(0.5f * q1, &ss4[1], &cc4[1]);
        sincosf(0.5f * q2, &ss4[2], &cc4[2]);
        sincosf(0.5f * q3, &ss4[3], &cc4[3]);
        float a[16];
        #pragma unroll
        for (int idx = 0; idx < 16; idx++) {
            float v = ((idx >> 3) & 1) ? ss4[0] : cc4[0];
            v *= ((idx >> 2) & 1) ? ss4[1] : cc4[1];
            v *= ((idx >> 1) & 1) ? ss4[2] : cc4[2];
            v *= (idx & 1) ? ss4[3] : cc4[3];
            a[idx] = v;
        }
        const float* M = &g_M[brx][0][0];
        float qo = 0.f;
        #pragma unroll
        for (int i2 = 0; i2 < 16; i2++) {
            float mi = 0.f;
            #pragma unroll
            for (int j = 0; j < 16; j++) mi = fmaf(M[i2 * 16 + j], a[j], mi);
            qo = fmaf(a[i2], mi, qo);
        }
        out[(size_t)brx * B + row0 + row] = qo + (brx ? __ldg(pb2) : __ldg(pb1));
    }
}

// ---------------------------------------------------------------------------
// Launch
// ---------------------------------------------------------------------------
extern "C" void kernel_launch(void* const* d_in, const int* in_sizes, int n_in,
                              void* d_out, int out_size) {
    const float* state  = (const float*)d_in[0];
    const float* action = (const float*)d_in[1];
    const float* q1_W1  = (const float*)d_in[2];
    const float* q1_b1  = (const float*)d_in[3];
    const float* q1_W2  = (const float*)d_in[4];
    const float* q1_b2  = (const float*)d_in[5];
    const float* q2_W1  = (const float*)d_in[6];
    const float* q2_b1  = (const float*)d_in[7];
    const float* q2_W2  = (const float*)d_in[8];
    const float* q2_b2  = (const float*)d_in[9];
    const float* q1_qw  = (const float*)d_in[10];
    const float* q2_qw  = (const float*)d_in[11];
    const float* q1_pw  = (const float*)d_in[12];
    const float* q1_pb  = (const float*)d_in[13];
    const float* q2_pw  = (const float*)d_in[14];
    const float* q2_pb  = (const float*)d_in[15];
    float* out = (float*)d_out;

    int B = in_sizes[0] / 128;

    cudaFuncSetAttribute(qc_hmma_kernel,
                         cudaFuncAttributeMaxDynamicSharedMemorySize, SMEM_BYTES);

    qc_prep_kernel<<<321, 512>>>(q1_W1, q2_W1, q1_qw, q2_qw, q1_pw, q2_pw);
    qc_hmma_kernel<<<B / 64, 512, SMEM_BYTES>>>(
        state, action, q1_b1, q2_b1, q1_W2, q2_W2, q1_b2, q2_b2,
        q1_pb, q2_pb, out, B);
}

// round 8
// speedup vs baseline: 1.4735x; 1.1032x over previous
#include <cuda_runtime.h>
#include <cuda_bf16.h>
#include <stdint.h>
#include <math.h>

#define NQ 4
#define DIM 16
#define KTOT 160

// ---------------- device globals ----------------
__device__ float g_M[2][DIM][DIM];                        // quadratic forms
// W' bf16 scratch: [branch(2)][chunk(5)][col 256][128B swizzled row]
__device__ __align__(16) unsigned char g_Wc[10 * 32768];

// ---------------- helpers ----------------
static __device__ __forceinline__ uint32_t smem_u32(const void* p) {
    uint32_t a;
    asm("{ .reg .u64 t; cvta.to.shared.u64 t, %1; cvt.u32.u64 %0, t; }" : "=r"(a) : "l"(p));
    return a;
}
static __device__ __forceinline__ void cp_async16(uint32_t dst, const void* src) {
    asm volatile("cp.async.cg.shared.global [%0], [%1], 16;" :: "r"(dst), "l"(src) : "memory");
}
static __device__ __forceinline__ void ldsm4(uint32_t* r, uint32_t addr) {
    asm volatile("ldmatrix.sync.aligned.m8n8.x4.shared.b16 {%0,%1,%2,%3}, [%4];"
                 : "=r"(r[0]), "=r"(r[1]), "=r"(r[2]), "=r"(r[3]) : "r"(addr));
}
static __device__ __forceinline__ void mma16816(float* d, const uint32_t* a,
                                                uint32_t b0, uint32_t b1) {
    asm volatile("mma.sync.aligned.m16n8k16.row.col.f32.bf16.bf16.f32 "
                 "{%0,%1,%2,%3}, {%4,%5,%6,%7}, {%8,%9}, {%0,%1,%2,%3};"
                 : "+f"(d[0]), "+f"(d[1]), "+f"(d[2]), "+f"(d[3])
                 : "r"(a[0]), "r"(a[1]), "r"(a[2]), "r"(a[3]), "r"(b0), "r"(b1));
}

// ---------------------------------------------------------------------------
// Prep kernel: blocks 0..319 build W scratch (bf16-hi duplicated in both K'
// halves: A'=[xh|xl] x B'=[wh|wh] == (xh+xl)*wh); block 320: quantum forms.
// Per-branch layout: [br*5+chunk][col 256][128B]; within the row, k-group
// (k'%64)/8 goes to position ((kg ^ (col&7))*8 + k'%8)*2 (XOR swizzle).
// ---------------------------------------------------------------------------
__global__ void qc_prep_kernel(const float* __restrict__ W11, const float* __restrict__ W12,
                               const float* __restrict__ qw1, const float* __restrict__ qw2,
                               const float* __restrict__ pw1, const float* __restrict__ pw2) {
    if (blockIdx.x < 320) {
        int id = blockIdx.x * 512 + threadIdx.x;   // 163840 = 512 cols * 320 k'
        int col = id / 320;
        int kp  = id - col * 320;
        int br = col >> 8, bcol = col & 255;
        const float* W = br ? W12 : W11;
        int k = (kp < 160) ? kp : kp - 160;
        float w = W[bcol * KTOT + k];
        __nv_bfloat16 val = __float2bfloat16_rn(w);    // hi in BOTH halves
        int chunk = kp >> 6, kin = kp & 63, kg = kin >> 3, ki = kin & 7;
        uint32_t off = (uint32_t)(br * 5 + chunk) * 32768 + (uint32_t)bcol * 128
                     + (uint32_t)(((kg ^ (bcol & 7)) * 8 + ki) * 2);
        *(unsigned short*)(g_Wc + off) = __bfloat16_as_ushort(val);
        return;
    }
    // ---- quantum setup (block 320, threads 0..31) ----
    __shared__ float sUr[2][DIM][DIM];
    __shared__ float sUi[2][DIM][DIM];
    int t = threadIdx.x;
    if (t < 32) {
        int br  = t >> 4;
        int col = t & 15;
        const float* qw = br ? qw2 : qw1;
        float vr[DIM], vi[DIM];
        #pragma unroll
        for (int k = 0; k < DIM; k++) { vr[k] = (k == col) ? 1.f : 0.f; vi[k] = 0.f; }

        for (int l = 0; l < 2; l++) {
            for (int q = 0; q < NQ; q++) {
                int s = 8 >> q;
                {   // RX
                    float th = qw[(l * NQ + q) * 3 + 0];
                    float c, sn; sincosf(0.5f * th, &sn, &c);
                    #pragma unroll
                    for (int i0 = 0; i0 < DIM; i0++) if (!(i0 & s)) {
                        int i1 = i0 | s;
                        float ar = vr[i0], ai = vi[i0], b_r = vr[i1], b_i = vi[i1];
                        vr[i0] = c * ar + sn * b_i;  vi[i0] = c * ai - sn * b_r;
                        vr[i1] = c * b_r + sn * ai;  vi[i1] = c * b_i - sn * ar;
                    }
                }
                {   // RY
                    float th = qw[(l * NQ + q) * 3 + 1];
                    float c, sn; sincosf(0.5f * th, &sn, &c);
                    #pragma unroll
                    for (int i0 = 0; i0 < DIM; i0++) if (!(i0 & s)) {
                        int i1 = i0 | s;
                        float ar = vr[i0], ai = vi[i0], b_r = vr[i1], b_i = vi[i1];
                        vr[i0] = c * ar - sn * b_r;  vi[i0] = c * ai - sn * b_i;
                        vr[i1] = sn * ar + c * b_r;  vi[i1] = sn * ai + c * b_i;
                    }
                }
                {   // RZ
                    float th = qw[(l * NQ + q) * 3 + 2];
                    float c, sn; sincosf(0.5f * th, &sn, &c);
                    #pragma unroll
                    for (int i0 = 0; i0 < DIM; i0++) {
                        float ar = vr[i0], ai = vi[i0];
                        if (i0 & s) { vr[i0] = c * ar - sn * ai; vi[i0] = c * ai + sn * ar; }
                        else        { vr[i0] = c * ar + sn * ai; vi[i0] = c * ai - sn * ar; }
                    }
                }
            }
            const int scs[4] = {8, 4, 2, 1};
            const int sts[4] = {4, 2, 1, 8};
            #pragma unroll
            for (int p = 0; p < 4; p++) {
                int sc = scs[p], st = sts[p];
                #pragma unroll
                for (int i0 = 0; i0 < DIM; i0++)
                    if ((i0 & sc) && !(i0 & st)) {
                        int i1 = i0 | st;
                        float tr = vr[i0], ti = vi[i0];
                        vr[i0] = vr[i1]; vi[i0] = vi[i1];
                        vr[i1] = tr;     vi[i1] = ti;
                    }
            }
        }
        #pragma unroll
        for (int k = 0; k < DIM; k++) { sUr[br][k][col] = vr[k]; sUi[br][k][col] = vi[k]; }
    }
    __syncthreads();
    if (t < 32) {
        int br = t >> 4;
        int i  = t & 15;
        float pw = br ? pw2[0] : pw1[0];
        for (int j = 0; j < DIM; j++) {
            float acc = 0.f;
            #pragma unroll
            for (int k = 0; k < DIM; k++) {
                float d = (k < 8) ? 1.f : -1.f;
                acc += d * (sUr[br][k][i] * sUr[br][k][j] + sUi[br][k][i] * sUi[br][k][j]);
            }
            g_M[br][i][j] = acc * pw;
        }
    }
}

// ---------------------------------------------------------------------------
// Main HMMA kernel. CTA: 256 thr = 8 warps (wm = wid&1, wn = wid>>1, 4 values).
// CTA handles M=64 rows x N=256 cols of ONE branch (br = blockIdx.x & 1).
// K'=320 in five 64-k chunks, double-buffered cp.async. 2 CTAs/SM.
// smem map (bytes):
//   [0, 41984)        X tile: 64 rows x pitch 656B (xh @0..319, xl @320..639)
//   [41984, 107520)   W double buffer: 2 x 256 cols x 128B (swizzled)
// epilogue overlay in X region: ps @0 (4KB), sW2 @4096 (4KB), sB1 @8192 (1KB)
// ---------------------------------------------------------------------------
#define XOFF  0u
#define WOFF  41984u
#define SMEM_BYTES 107520

__global__ __launch_bounds__(256, 2)
void qc_hmma_kernel(const float* __restrict__ state, const float* __restrict__ action,
                    const float* __restrict__ b11, const float* __restrict__ b12,
                    const float* __restrict__ W21, const float* __restrict__ W22,
                    const float* __restrict__ b21, const float* __restrict__ b22,
                    const float* __restrict__ pb1, const float* __restrict__ pb2,
                    float* __restrict__ out, int B) {
    extern __shared__ char smem[];
    uint32_t sb = smem_u32(smem);
    int t = threadIdx.x, lane = t & 31, wid = t >> 5;
    int wm = wid & 1, wn = wid >> 1;           // wn in 0..3
    int mtile = blockIdx.x >> 1, br = blockIdx.x & 1;
    int row0 = mtile * 64;
    const unsigned char* wsrc = g_Wc + (size_t)br * 5 * 32768;

    // prefetch W chunk 0 (fully coalesced: contiguous 16B per lane)
    #pragma unroll
    for (int i = 0; i < 8; i++)
        cp_async16(sb + WOFF + (uint32_t)(t * 16 + i * 4096), wsrc + t * 16 + i * 4096);
    asm volatile("cp.async.commit_group;" ::: "memory");

    // X tile: load fp32, split to hi/lo bf16, store to smem (1280 tasks)
    #pragma unroll
    for (int p = 0; p < 5; p++) {
        int task = t + p * 256;
        int r = task / 20, g = task - r * 20;
        const float* src = (g < 16) ? state + (size_t)(row0 + r) * 128 + g * 8
                                    : action + (size_t)(row0 + r) * 32 + (g - 16) * 8;
        float4 va = *(const float4*)src;
        float4 vb = *(const float4*)(src + 4);
        float v[8] = {va.x, va.y, va.z, va.w, vb.x, vb.y, vb.z, vb.w};
        uint32_t hp[4], lp[4];
        #pragma unroll
        for (int i = 0; i < 4; i++) {
            __nv_bfloat16 h0 = __float2bfloat16_rn(v[2 * i]);
            __nv_bfloat16 h1 = __float2bfloat16_rn(v[2 * i + 1]);
            __nv_bfloat16 l0 = __float2bfloat16_rn(v[2 * i] - __bfloat162float(h0));
            __nv_bfloat16 l1 = __float2bfloat16_rn(v[2 * i + 1] - __bfloat162float(h1));
            hp[i] = (uint32_t)__bfloat16_as_ushort(h0) | ((uint32_t)__bfloat16_as_ushort(h1) << 16);
            lp[i] = (uint32_t)__bfloat16_as_ushort(l0) | ((uint32_t)__bfloat16_as_ushort(l1) << 16);
        }
        uint32_t base = sb + XOFF + (uint32_t)(r * 656 + g * 16);
        asm volatile("st.shared.v4.b32 [%0], {%1,%2,%3,%4};"
                     :: "r"(base), "r"(hp[0]), "r"(hp[1]), "r"(hp[2]), "r"(hp[3]) : "memory");
        asm volatile("st.shared.v4.b32 [%0], {%1,%2,%3,%4};"
                     :: "r"(base + 320), "r"(lp[0]), "r"(lp[1]), "r"(lp[2]), "r"(lp[3]) : "memory");
    }

    // per-lane ldmatrix bases
    uint32_t a_base = sb + XOFF + (uint32_t)((wm * 32 + (lane & 15)) * 656 + (lane >> 4) * 16);
    uint32_t b_base = (uint32_t)((wn * 64 + (lane & 15)) * 128);
    uint32_t ssx = lane & 7, hh = lane >> 4;

    float acc[2][8][4];
    #pragma unroll
    for (int m = 0; m < 2; m++)
        #pragma unroll
        for (int n = 0; n < 8; n++)
            #pragma unroll
            for (int j = 0; j < 4; j++) acc[m][n][j] = 0.f;

    #pragma unroll 1
    for (int c = 0; c < 5; c++) {
        asm volatile("cp.async.wait_group 0;" ::: "memory");
        __syncthreads();
        if (c < 4) {   // prefetch next chunk into other buffer
            const unsigned char* src = wsrc + (size_t)(c + 1) * 32768;
            uint32_t dst = sb + WOFF + (uint32_t)(((c + 1) & 1) * 32768);
            #pragma unroll
            for (int i = 0; i < 8; i++)
                cp_async16(dst + (uint32_t)(t * 16 + i * 4096), src + t * 16 + i * 4096);
            asm volatile("cp.async.commit_group;" ::: "memory");
        }
        uint32_t wbuf = sb + WOFF + (uint32_t)((c & 1) * 32768);
        #pragma unroll
        for (int ks = 0; ks < 4; ks++) {
            uint32_t a0[4], a1[4];
            uint32_t koff = (uint32_t)((c * 64 + ks * 16) * 2);
            ldsm4(a0, a_base + koff);
            ldsm4(a1, a_base + 16 * 656 + koff);
            uint32_t kgx = (((uint32_t)(ks * 2) + hh) ^ ssx) << 4;
            #pragma unroll
            for (int n2 = 0; n2 < 4; n2++) {
                uint32_t bfr[4];
                ldsm4(bfr, wbuf + b_base + (uint32_t)(n2 * 2048) + kgx);
                mma16816(acc[0][2 * n2],     a0, bfr[0], bfr[2]);
                mma16816(acc[0][2 * n2 + 1], a0, bfr[1], bfr[3]);
                mma16816(acc[1][2 * n2],     a1, bfr[0], bfr[2]);
                mma16816(acc[1][2 * n2 + 1], a1, bfr[1], bfr[3]);
            }
        }
    }

    // ---------------- epilogue ----------------
    __syncthreads();   // all warps done reading X region
    float* ps  = (float*)(smem + 0);        // [4][64][4]
    float* sW2 = (float*)(smem + 4096);     // [256][4]
    float* sB1 = (float*)(smem + 8192);     // [256]
    {
        int col = t;
        const float* W2 = br ? W22 : W21;
        sW2[col * 4 + 0] = W2[0 * 256 + col];
        sW2[col * 4 + 1] = W2[1 * 256 + col];
        sW2[col * 4 + 2] = W2[2 * 256 + col];
        sW2[col * 4 + 3] = W2[3 * 256 + col];
        sB1[col] = br ? b12[col] : b11[col];
    }
    __syncthreads();

    float p[4][4];
    #pragma unroll
    for (int s = 0; s < 4; s++)
        #pragma unroll
        for (int j = 0; j < 4; j++) p[s][j] = 0.f;

    #pragma unroll
    for (int m = 0; m < 2; m++)
        #pragma unroll
        for (int n = 0; n < 8; n++) {
            int c0 = wn * 64 + n * 8 + 2 * (lane & 3);
            float bb0 = sB1[c0], bb1 = sB1[c0 + 1];
            float h0 = fmaxf(acc[m][n][0] + bb0, 0.f);
            float h1 = fmaxf(acc[m][n][1] + bb1, 0.f);
            float h2 = fmaxf(acc[m][n][2] + bb0, 0.f);
            float h3 = fmaxf(acc[m][n][3] + bb1, 0.f);
            const float4 w0 = *(const float4*)(sW2 + c0 * 4);
            const float4 w1 = *(const float4*)(sW2 + (c0 + 1) * 4);
            p[2*m][0] = fmaf(w0.x, h0, fmaf(w1.x, h1, p[2*m][0]));
            p[2*m][1] = fmaf(w0.y, h0, fmaf(w1.y, h1, p[2*m][1]));
            p[2*m][2] = fmaf(w0.z, h0, fmaf(w1.z, h1, p[2*m][2]));
            p[2*m][3] = fmaf(w0.w, h0, fmaf(w1.w, h1, p[2*m][3]));
            p[2*m+1][0] = fmaf(w0.x, h2, fmaf(w1.x, h3, p[2*m+1][0]));
            p[2*m+1][1] = fmaf(w0.y, h2, fmaf(w1.y, h3, p[2*m+1][1]));
            p[2*m+1][2] = fmaf(w0.z, h2, fmaf(w1.z, h3, p[2*m+1][2]));
            p[2*m+1][3] = fmaf(w0.w, h2, fmaf(w1.w, h3, p[2*m+1][3]));
        }
    #pragma unroll
    for (int off = 1; off < 4; off <<= 1)
        #pragma unroll
        for (int s = 0; s < 4; s++)
            #pragma unroll
            for (int j = 0; j < 4; j++)
                p[s][j] += __shfl_xor_sync(0xffffffffu, p[s][j], off);

    if ((lane & 3) == 0) {
        int rq = lane >> 2;
        #pragma unroll
        for (int s = 0; s < 4; s++) {
            int row = wm * 32 + (s >> 1) * 16 + (s & 1) * 8 + rq;
            *(float4*)(ps + ((size_t)wn * 64 + row) * 4) =
                make_float4(p[s][0], p[s][1], p[s][2], p[s][3]);
        }
    }
    __syncthreads();

    if (t < 64) {
        int row = t;
        const float4* psv = (const float4*)ps;
        float4 s0 = psv[0 * 64 + row];
        float4 s1 = psv[1 * 64 + row];
        float4 s2 = psv[2 * 64 + row];
        float4 s3 = psv[3 * 64 + row];
        const float* b2 = br ? b22 : b21;
        float q0 = s0.x + s1.x + s2.x + s3.x + __ldg(b2 + 0);
        float q1 = s0.y + s1.y + s2.y + s3.y + __ldg(b2 + 1);
        float q2 = s0.z + s1.z + s2.z + s3.z + __ldg(b2 + 2);
        float q3 = s0.w + s1.w + s2.w + s3.w + __ldg(b2 + 3);

        float cc4[4], ss4[4];
        sincosf(0.5f * q0, &ss4[0], &cc4[0]);
        sincosf(0.5f * q1, &ss4[1], &cc4[1]);
        sincosf(0.5f * q2, &ss4[2], &cc4[2]);
        sincosf(0.5f * q3, &ss4[3], &cc4[3]);
        float a[16];
        #pragma unroll
        for (int idx = 0; idx < 16; idx++) {
            float v = ((idx >> 3) & 1) ? ss4[0] : cc4[0];
            v *= ((idx >> 2) & 1) ? ss4[1] : cc4[1];
            v *= ((idx >> 1) & 1) ? ss4[2] : cc4[2];
            v *= (idx & 1) ? ss4[3] : cc4[3];
            a[idx] = v;
        }
        const float* M = &g_M[br][0][0];
        float qo = 0.f;
        #pragma unroll
        for (int i2 = 0; i2 < 16; i2++) {
            float mi = 0.f;
            #pragma unroll
            for (int j = 0; j < 16; j++) mi = fmaf(M[i2 * 16 + j], a[j], mi);
            qo = fmaf(a[i2], mi, qo);
        }
        out[(size_t)br * B + row0 + row] = qo + (br ? __ldg(pb2) : __ldg(pb1));
    }
}

// ---------------------------------------------------------------------------
// Launch
// ---------------------------------------------------------------------------
extern "C" void kernel_launch(void* const* d_in, const int* in_sizes, int n_in,
                              void* d_out, int out_size) {
    const float* state  = (const float*)d_in[0];
    const float* action = (const float*)d_in[1];
    const float* q1_W1  = (const float*)d_in[2];
    const float* q1_b1  = (const float*)d_in[3];
    const float* q1_W2  = (const float*)d_in[4];
    const float* q1_b2  = (const float*)d_in[5];
    const float* q2_W1  = (const float*)d_in[6];
    const float* q2_b1  = (const float*)d_in[7];
    const float* q2_W2  = (const float*)d_in[8];
    const float* q2_b2  = (const float*)d_in[9];
    const float* q1_qw  = (const float*)d_in[10];
    const float* q2_qw  = (const float*)d_in[11];
    const float* q1_pw  = (const float*)d_in[12];
    const float* q1_pb  = (const float*)d_in[13];
    const float* q2_pw  = (const float*)d_in[14];
    const float* q2_pb  = (const float*)d_in[15];
    float* out = (float*)d_out;

    int B = in_sizes[0] / 128;

    cudaFuncSetAttribute(qc_hmma_kernel,
                         cudaFuncAttributeMaxDynamicSharedMemorySize, SMEM_BYTES);

    qc_prep_kernel<<<321, 512>>>(q1_W1, q2_W1, q1_qw, q2_qw, q1_pw, q2_pw);
    qc_hmma_kernel<<<(B / 64) * 2, 256, SMEM_BYTES>>>(
        state, action, q1_b1, q2_b1, q1_W2, q2_W2, q1_b2, q2_b2,
        q1_pb, q2_pb, out, B);
}

// round 11
// speedup vs baseline: 1.5873x; 1.0773x over previous
#include <cuda_runtime.h>
#include <cuda_bf16.h>
#include <stdint.h>
#include <math.h>

#define NQ 4
#define DIM 16
#define KTOT 160

// ---------------- device globals ----------------
__device__ float g_M[2][DIM][DIM];                        // quadratic forms
// W' bf16 scratch: [branch(2)][chunk(5)][col 256][128B swizzled row]
__device__ __align__(16) unsigned char g_Wc[10 * 32768];

// ---------------- helpers ----------------
static __device__ __forceinline__ uint32_t smem_u32(const void* p) {
    uint32_t a;
    asm("{ .reg .u64 t; cvta.to.shared.u64 t, %1; cvt.u32.u64 %0, t; }" : "=r"(a) : "l"(p));
    return a;
}
static __device__ __forceinline__ void cp_async16(uint32_t dst, const void* src) {
    asm volatile("cp.async.cg.shared.global [%0], [%1], 16;" :: "r"(dst), "l"(src) : "memory");
}
static __device__ __forceinline__ void ldsm4(uint32_t* r, uint32_t addr) {
    asm volatile("ldmatrix.sync.aligned.m8n8.x4.shared.b16 {%0,%1,%2,%3}, [%4];"
                 : "=r"(r[0]), "=r"(r[1]), "=r"(r[2]), "=r"(r[3]) : "r"(addr));
}
static __device__ __forceinline__ void mma16816(float* d, const uint32_t* a,
                                                uint32_t b0, uint32_t b1) {
    asm volatile("mma.sync.aligned.m16n8k16.row.col.f32.bf16.bf16.f32 "
                 "{%0,%1,%2,%3}, {%4,%5,%6,%7}, {%8,%9}, {%0,%1,%2,%3};"
                 : "+f"(d[0]), "+f"(d[1]), "+f"(d[2]), "+f"(d[3])
                 : "r"(a[0]), "r"(a[1]), "r"(a[2]), "r"(a[3]), "r"(b0), "r"(b1));
}

// ---------------------------------------------------------------------------
// Prep kernel: blocks 0..319 build W scratch (bf16-hi duplicated in both K'
// halves: A'=[xh|xl] x B'=[wh|wh] == (xh+xl)*wh); block 320: quantum forms.
// Per-branch layout: [br*5+chunk][col 256][128B]; within the row, k-group
// (k'%64)/8 goes to position ((kg ^ (col&7))*8 + k'%8)*2 (XOR swizzle).
// ---------------------------------------------------------------------------
__global__ void qc_prep_kernel(const float* __restrict__ W11, const float* __restrict__ W12,
                               const float* __restrict__ qw1, const float* __restrict__ qw2,
                               const float* __restrict__ pw1, const float* __restrict__ pw2) {
    if (blockIdx.x < 320) {
        int id = blockIdx.x * 512 + threadIdx.x;   // 163840 = 512 cols * 320 k'
        int col = id / 320;
        int kp  = id - col * 320;
        int br = col >> 8, bcol = col & 255;
        const float* W = br ? W12 : W11;
        int k = (kp < 160) ? kp : kp - 160;
        float w = W[bcol * KTOT + k];
        __nv_bfloat16 val = __float2bfloat16_rn(w);    // hi in BOTH halves
        int chunk = kp >> 6, kin = kp & 63, kg = kin >> 3, ki = kin & 7;
        uint32_t off = (uint32_t)(br * 5 + chunk) * 32768 + (uint32_t)bcol * 128
                     + (uint32_t)(((kg ^ (bcol & 7)) * 8 + ki) * 2);
        *(unsigned short*)(g_Wc + off) = __bfloat16_as_ushort(val);
        return;
    }
    // ---- quantum setup (block 320, threads 0..31) ----
    __shared__ float sUr[2][DIM][DIM];
    __shared__ float sUi[2][DIM][DIM];
    int t = threadIdx.x;
    if (t < 32) {
        int br  = t >> 4;
        int col = t & 15;
        const float* qw = br ? qw2 : qw1;
        float vr[DIM], vi[DIM];
        #pragma unroll
        for (int k = 0; k < DIM; k++) { vr[k] = (k == col) ? 1.f : 0.f; vi[k] = 0.f; }

        for (int l = 0; l < 2; l++) {
            for (int q = 0; q < NQ; q++) {
                int s = 8 >> q;
                {   // RX
                    float th = qw[(l * NQ + q) * 3 + 0];
                    float c, sn; sincosf(0.5f * th, &sn, &c);
                    #pragma unroll
                    for (int i0 = 0; i0 < DIM; i0++) if (!(i0 & s)) {
                        int i1 = i0 | s;
                        float ar = vr[i0], ai = vi[i0], b_r = vr[i1], b_i = vi[i1];
                        vr[i0] = c * ar + sn * b_i;  vi[i0] = c * ai - sn * b_r;
                        vr[i1] = c * b_r + sn * ai;  vi[i1] = c * b_i - sn * ar;
                    }
                }
                {   // RY
                    float th = qw[(l * NQ + q) * 3 + 1];
                    float c, sn; sincosf(0.5f * th, &sn, &c);
                    #pragma unroll
                    for (int i0 = 0; i0 < DIM; i0++) if (!(i0 & s)) {
                        int i1 = i0 | s;
                        float ar = vr[i0], ai = vi[i0], b_r = vr[i1], b_i = vi[i1];
                        vr[i0] = c * ar - sn * b_r;  vi[i0] = c * ai - sn * b_i;
                        vr[i1] = sn * ar + c * b_r;  vi[i1] = sn * ai + c * b_i;
                    }
                }
                {   // RZ
                    float th = qw[(l * NQ + q) * 3 + 2];
                    float c, sn; sincosf(0.5f * th, &sn, &c);
                    #pragma unroll
                    for (int i0 = 0; i0 < DIM; i0++) {
                        float ar = vr[i0], ai = vi[i0];
                        if (i0 & s) { vr[i0] = c * ar - sn * ai; vi[i0] = c * ai + sn * ar; }
                        else        { vr[i0] = c * ar + sn * ai; vi[i0] = c * ai - sn * ar; }
                    }
                }
            }
            const int scs[4] = {8, 4, 2, 1};
            const int sts[4] = {4, 2, 1, 8};
            #pragma unroll
            for (int p = 0; p < 4; p++) {
                int sc = scs[p], st = sts[p];
                #pragma unroll
                for (int i0 = 0; i0 < DIM; i0++)
                    if ((i0 & sc) && !(i0 & st)) {
                        int i1 = i0 | st;
                        float tr = vr[i0], ti = vi[i0];
                        vr[i0] = vr[i1]; vi[i0] = vi[i1];
                        vr[i1] = tr;     vi[i1] = ti;
                    }
            }
        }
        #pragma unroll
        for (int k = 0; k < DIM; k++) { sUr[br][k][col] = vr[k]; sUi[br][k][col] = vi[k]; }
    }
    __syncthreads();
    if (t < 32) {
        int br = t >> 4;
        int i  = t & 15;
        float pw = br ? pw2[0] : pw1[0];
        for (int j = 0; j < DIM; j++) {
            float acc = 0.f;
            #pragma unroll
            for (int k = 0; k < DIM; k++) {
                float d = (k < 8) ? 1.f : -1.f;
                acc += d * (sUr[br][k][i] * sUr[br][k][j] + sUi[br][k][i] * sUi[br][k][j]);
            }
            g_M[br][i][j] = acc * pw;
        }
    }
}

// ---------------------------------------------------------------------------
// Main HMMA kernel. CTA: 256 thr = 8 warps (wm = wid&1, wn = wid>>1, 4 values).
// CTA handles M=64 rows x N=256 cols of ONE branch (br = blockIdx.x & 1).
// K'=320 in five 64-k chunks, double-buffered cp.async. 2 CTAs/SM.
// Mainloop fully unrolled; per-ks: 6 LDSMs first, then 16 MMAs.
// smem map (bytes):
//   [0, 41984)        X tile: 64 rows x pitch 656B (xh @0..319, xl @320..639)
//   [41984, 107520)   W double buffer: 2 x 256 cols x 128B (swizzled)
// epilogue overlay in X region: ps @0 (4KB), sW2 @4096 (4KB), sB1 @8192 (1KB)
// ---------------------------------------------------------------------------
#define XOFF  0u
#define WOFF  41984u
#define SMEM_BYTES 107520

__global__ __launch_bounds__(256, 2)
void qc_hmma_kernel(const float* __restrict__ state, const float* __restrict__ action,
                    const float* __restrict__ b11, const float* __restrict__ b12,
                    const float* __restrict__ W21, const float* __restrict__ W22,
                    const float* __restrict__ b21, const float* __restrict__ b22,
                    const float* __restrict__ pb1, const float* __restrict__ pb2,
                    float* __restrict__ out, int B) {
    extern __shared__ char smem[];
    uint32_t sb = smem_u32(smem);
    int t = threadIdx.x, lane = t & 31, wid = t >> 5;
    int wm = wid & 1, wn = wid >> 1;           // wn in 0..3
    int mtile = blockIdx.x >> 1, br = blockIdx.x & 1;
    int row0 = mtile * 64;
    const unsigned char* wsrc = g_Wc + (size_t)br * 5 * 32768;

    // prefetch W chunk 0 (fully coalesced: contiguous 16B per lane)
    #pragma unroll
    for (int i = 0; i < 8; i++)
        cp_async16(sb + WOFF + (uint32_t)(t * 16 + i * 4096), wsrc + t * 16 + i * 4096);
    asm volatile("cp.async.commit_group;" ::: "memory");

    // X tile: load fp32, split to hi/lo bf16, store to smem (1280 tasks)
    #pragma unroll
    for (int p = 0; p < 5; p++) {
        int task = t + p * 256;
        int r = task / 20, g = task - r * 20;
        const float* src = (g < 16) ? state + (size_t)(row0 + r) * 128 + g * 8
                                    : action + (size_t)(row0 + r) * 32 + (g - 16) * 8;
        float4 va = *(const float4*)src;
        float4 vb = *(const float4*)(src + 4);
        float v[8] = {va.x, va.y, va.z, va.w, vb.x, vb.y, vb.z, vb.w};
        uint32_t hp[4], lp[4];
        #pragma unroll
        for (int i = 0; i < 4; i++) {
            __nv_bfloat16 h0 = __float2bfloat16_rn(v[2 * i]);
            __nv_bfloat16 h1 = __float2bfloat16_rn(v[2 * i + 1]);
            __nv_bfloat16 l0 = __float2bfloat16_rn(v[2 * i] - __bfloat162float(h0));
            __nv_bfloat16 l1 = __float2bfloat16_rn(v[2 * i + 1] - __bfloat162float(h1));
            hp[i] = (uint32_t)__bfloat16_as_ushort(h0) | ((uint32_t)__bfloat16_as_ushort(h1) << 16);
            lp[i] = (uint32_t)__bfloat16_as_ushort(l0) | ((uint32_t)__bfloat16_as_ushort(l1) << 16);
        }
        uint32_t base = sb + XOFF + (uint32_t)(r * 656 + g * 16);
        asm volatile("st.shared.v4.b32 [%0], {%1,%2,%3,%4};"
                     :: "r"(base), "r"(hp[0]), "r"(hp[1]), "r"(hp[2]), "r"(hp[3]) : "memory");
        asm volatile("st.shared.v4.b32 [%0], {%1,%2,%3,%4};"
                     :: "r"(base + 320), "r"(lp[0]), "r"(lp[1]), "r"(lp[2]), "r"(lp[3]) : "memory");
    }

    // per-lane ldmatrix bases
    uint32_t a_base = sb + XOFF + (uint32_t)((wm * 32 + (lane & 15)) * 656 + (lane >> 4) * 16);
    uint32_t b_base = (uint32_t)((wn * 64 + (lane & 15)) * 128);
    uint32_t ssx = lane & 7, hh = lane >> 4;

    // precomputed B addresses: baddr[buf][ks] (n2 offset is an immediate)
    uint32_t baddr[2][4];
    #pragma unroll
    for (int ks = 0; ks < 4; ks++) {
        uint32_t kgx = (((uint32_t)(ks * 2) + hh) ^ ssx) << 4;
        baddr[0][ks] = sb + WOFF + b_base + kgx;
        baddr[1][ks] = sb + WOFF + 32768u + b_base + kgx;
    }

    float acc[2][8][4];
    #pragma unroll
    for (int m = 0; m < 2; m++)
        #pragma unroll
        for (int n = 0; n < 8; n++)
            #pragma unroll
            for (int j = 0; j < 4; j++) acc[m][n][j] = 0.f;

    #pragma unroll
    for (int c = 0; c < 5; c++) {
        asm volatile("cp.async.wait_group 0;" ::: "memory");
        __syncthreads();
        if (c < 4) {   // prefetch next chunk into other buffer
            const unsigned char* src = wsrc + (size_t)(c + 1) * 32768;
            uint32_t dst = sb + WOFF + (uint32_t)(((c + 1) & 1) * 32768);
            #pragma unroll
            for (int i = 0; i < 8; i++)
                cp_async16(dst + (uint32_t)(t * 16 + i * 4096), src + t * 16 + i * 4096);
            asm volatile("cp.async.commit_group;" ::: "memory");
        }
        const int buf = c & 1;
        #pragma unroll
        for (int ks = 0; ks < 4; ks++) {
            const uint32_t koff = (uint32_t)((c * 64 + ks * 16) * 2);
            // --- all fragment loads first (independent issues) ---
            uint32_t a0[4], a1[4], bfr[4][4];
            ldsm4(a0, a_base + koff);
            ldsm4(a1, a_base + 16 * 656 + koff);
            ldsm4(bfr[0], baddr[buf][ks]);
            ldsm4(bfr[1], baddr[buf][ks] + 2048);
            ldsm4(bfr[2], baddr[buf][ks] + 4096);
            ldsm4(bfr[3], baddr[buf][ks] + 6144);
            // --- then 16 MMAs ---
            #pragma unroll
            for (int n2 = 0; n2 < 4; n2++) {
                mma16816(acc[0][2 * n2],     a0, bfr[n2][0], bfr[n2][2]);
                mma16816(acc[0][2 * n2 + 1], a0, bfr[n2][1], bfr[n2][3]);
                mma16816(acc[1][2 * n2],     a1, bfr[n2][0], bfr[n2][2]);
                mma16816(acc[1][2 * n2 + 1], a1, bfr[n2][1], bfr[n2][3]);
            }
        }
    }

    // ---------------- epilogue ----------------
    __syncthreads();   // all warps done reading X region
    float* ps  = (float*)(smem + 0);        // [4][64][4]
    float* sW2 = (float*)(smem + 4096);     // [256][4]
    float* sB1 = (float*)(smem + 8192);     // [256]
    {
        int col = t;
        const float* W2 = br ? W22 : W21;
        sW2[col * 4 + 0] = W2[0 * 256 + col];
        sW2[col * 4 + 1] = W2[1 * 256 + col];
        sW2[col * 4 + 2] = W2[2 * 256 + col];
        sW2[col * 4 + 3] = W2[3 * 256 + col];
        sB1[col] = br ? b12[col] : b11[col];
    }
    __syncthreads();

    float p[4][4];
    #pragma unroll
    for (int s = 0; s < 4; s++)
        #pragma unroll
        for (int j = 0; j < 4; j++) p[s][j] = 0.f;

    #pragma unroll
    for (int m = 0; m < 2; m++)
        #pragma unroll
        for (int n = 0; n < 8; n++) {
            int c0 = wn * 64 + n * 8 + 2 * (lane & 3);
            float bb0 = sB1[c0], bb1 = sB1[c0 + 1];
            float h0 = fmaxf(acc[m][n][0] + bb0, 0.f);
            float h1 = fmaxf(acc[m][n][1] + bb1, 0.f);
            float h2 = fmaxf(acc[m][n][2] + bb0, 0.f);
            float h3 = fmaxf(acc[m][n][3] + bb1, 0.f);
            const float4 w0 = *(const float4*)(sW2 + c0 * 4);
            const float4 w1 = *(const float4*)(sW2 + (c0 + 1) * 4);
            p[2*m][0] = fmaf(w0.x, h0, fmaf(w1.x, h1, p[2*m][0]));
            p[2*m][1] = fmaf(w0.y, h0, fmaf(w1.y, h1, p[2*m][1]));
            p[2*m][2] = fmaf(w0.z, h0, fmaf(w1.z, h1, p[2*m][2]));
            p[2*m][3] = fmaf(w0.w, h0, fmaf(w1.w, h1, p[2*m][3]));
            p[2*m+1][0] = fmaf(w0.x, h2, fmaf(w1.x, h3, p[2*m+1][0]));
            p[2*m+1][1] = fmaf(w0.y, h2, fmaf(w1.y, h3, p[2*m+1][1]));
            p[2*m+1][2] = fmaf(w0.z, h2, fmaf(w1.z, h3, p[2*m+1][2]));
            p[2*m+1][3] = fmaf(w0.w, h2, fmaf(w1.w, h3, p[2*m+1][3]));
        }
    #pragma unroll
    for (int off = 1; off < 4; off <<= 1)
        #pragma unroll
        for (int s = 0; s < 4; s++)
            #pragma unroll
            for (int j = 0; j < 4; j++)
                p[s][j] += __shfl_xor_sync(0xffffffffu, p[s][j], off);

    if ((lane & 3) == 0) {
        int rq = lane >> 2;
        #pragma unroll
        for (int s = 0; s < 4; s++) {
            int row = wm * 32 + (s >> 1) * 16 + (s & 1) * 8 + rq;
            *(float4*)(ps + ((size_t)wn * 64 + row) * 4) =
                make_float4(p[s][0], p[s][1], p[s][2], p[s][3]);
        }
    }
    __syncthreads();

    if (t < 64) {
        int row = t;
        const float4* psv = (const float4*)ps;
        float4 s0 = psv[0 * 64 + row];
        float4 s1 = psv[1 * 64 + row];
        float4 s2 = psv[2 * 64 + row];
        float4 s3 = psv[3 * 64 + row];
        const float* b2 = br ? b22 : b21;
        float q0 = s0.x + s1.x + s2.x + s3.x + __ldg(b2 + 0);
        float q1 = s0.y + s1.y + s2.y + s3.y + __ldg(b2 + 1);
        float q2 = s0.z + s1.z + s2.z + s3.z + __ldg(b2 + 2);
        float q3 = s0.w + s1.w + s2.w + s3.w + __ldg(b2 + 3);

        float cc4[4], ss4[4];
        sincosf(0.5f * q0, &ss4[0], &cc4[0]);
        sincosf(0.5f * q1, &ss4[1], &cc4[1]);
        sincosf(0.5f * q2, &ss4[2], &cc4[2]);
        sincosf(0.5f * q3, &ss4[3], &cc4[3]);
        float a[16];
        #pragma unroll
        for (int idx = 0; idx < 16; idx++) {
            float v = ((idx >> 3) & 1) ? ss4[0] : cc4[0];
            v *= ((idx >> 2) & 1) ? ss4[1] : cc4[1];
            v *= ((idx >> 1) & 1) ? ss4[2] : cc4[2];
            v *= (idx & 1) ? ss4[3] : cc4[3];
            a[idx] = v;
        }
        const float* M = &g_M[br][0][0];
        float qo = 0.f;
        #pragma unroll
        for (int i2 = 0; i2 < 16; i2++) {
            float mi = 0.f;
            #pragma unroll
            for (int j = 0; j < 16; j++) mi = fmaf(M[i2 * 16 + j], a[j], mi);
            qo = fmaf(a[i2], mi, qo);
        }
        out[(size_t)br * B + row0 + row] = qo + (br ? __ldg(pb2) : __ldg(pb1));
    }
}

// ---------------------------------------------------------------------------
// Launch
// ---------------------------------------------------------------------------
extern "C" void kernel_launch(void* const* d_in, const int* in_sizes, int n_in,
                              void* d_out, int out_size) {
    const float* state  = (const float*)d_in[0];
    const float* action = (const float*)d_in[1];
    const float* q1_W1  = (const float*)d_in[2];
    const float* q1_b1  = (const float*)d_in[3];
    const float* q1_W2  = (const float*)d_in[4];
    const float* q1_b2  = (const float*)d_in[5];
    const float* q2_W1  = (const float*)d_in[6];
    const float* q2_b1  = (const float*)d_in[7];
    const float* q2_W2  = (const float*)d_in[8];
    const float* q2_b2  = (const float*)d_in[9];
    const float* q1_qw  = (const float*)d_in[10];
    const float* q2_qw  = (const float*)d_in[11];
    const float* q1_pw  = (const float*)d_in[12];
    const float* q1_pb  = (const float*)d_in[13];
    const float* q2_pw  = (const float*)d_in[14];
    const float* q2_pb  = (const float*)d_in[15];
    float* out = (float*)d_out;

    int B = in_sizes[0] / 128;

    cudaFuncSetAttribute(qc_hmma_kernel,
                         cudaFuncAttributeMaxDynamicSharedMemorySize, SMEM_BYTES);

    qc_prep_kernel<<<321, 512>>>(q1_W1, q2_W1, q1_qw, q2_qw, q1_pw, q2_pw);
    qc_hmma_kernel<<<(B / 64) * 2, 256, SMEM_BYTES>>>(
        state, action, q1_b1, q2_b1, q1_W2, q2_W2, q1_b2, q2_b2,
        q1_pb, q2_pb, out, B);
}

// round 13
// speedup vs baseline: 2.0879x; 1.3154x over previous
#include <cuda_runtime.h>
#include <cuda_fp16.h>
#include <stdint.h>
#include <math.h>

#define NQ 4
#define DIM 16
#define KTOT 160

// ---------------- device globals ----------------
__device__ float g_M[2][DIM][DIM];                        // quadratic forms
// W fp16 scratch: [branch(2)][chunk(3, k64 each, zero-padded past 160)][col 256][128B swizzled]
__device__ __align__(16) unsigned char g_Wc[6 * 32768];

// ---------------- helpers ----------------
static __device__ __forceinline__ uint32_t smem_u32(const void* p) {
    uint32_t a;
    asm("{ .reg .u64 t; cvta.to.shared.u64 t, %1; cvt.u32.u64 %0, t; }" : "=r"(a) : "l"(p));
    return a;
}
static __device__ __forceinline__ void cp_async16(uint32_t dst, const void* src) {
    asm volatile("cp.async.cg.shared.global [%0], [%1], 16;" :: "r"(dst), "l"(src) : "memory");
}
static __device__ __forceinline__ void ldsm4(uint32_t* r, uint32_t addr) {
    asm volatile("ldmatrix.sync.aligned.m8n8.x4.shared.b16 {%0,%1,%2,%3}, [%4];"
                 : "=r"(r[0]), "=r"(r[1]), "=r"(r[2]), "=r"(r[3]) : "r"(addr));
}
static __device__ __forceinline__ void mma16816(float* d, const uint32_t* a,
                                                uint32_t b0, uint32_t b1) {
    asm volatile("mma.sync.aligned.m16n8k16.row.col.f32.f16.f16.f32 "
                 "{%0,%1,%2,%3}, {%4,%5,%6,%7}, {%8,%9}, {%0,%1,%2,%3};"
                 : "+f"(d[0]), "+f"(d[1]), "+f"(d[2]), "+f"(d[3])
                 : "r"(a[0]), "r"(a[1]), "r"(a[2]), "r"(a[3]), "r"(b0), "r"(b1));
}

// ---------------------------------------------------------------------------
// Prep kernel: blocks 0..191 build fp16 W scratch (zero-padded k 160..191);
// block 192: quantum quadratic forms.
// Layout: [br*3+chunk][col 256][128B]; within the row, k-group (k%64)/8 at
// position ((kg ^ (col&7))*8 + k%8)*2 (XOR swizzle, conflict-free ldmatrix).
// ---------------------------------------------------------------------------
__global__ void qc_prep_kernel(const float* __restrict__ W11, const float* __restrict__ W12,
                               const float* __restrict__ qw1, const float* __restrict__ qw2,
                               const float* __restrict__ pw1, const float* __restrict__ pw2) {
    if (blockIdx.x < 192) {
        int id = blockIdx.x * 512 + threadIdx.x;   // 98304 = 512 cols * 192 k
        int col = id / 192;
        int kp  = id - col * 192;
        int br = col >> 8, bcol = col & 255;
        const float* W = br ? W12 : W11;
        float w = (kp < KTOT) ? W[bcol * KTOT + kp] : 0.f;
        __half val = __float2half_rn(w);
        int chunk = kp >> 6, kin = kp & 63, kg = kin >> 3, ki = kin & 7;
        uint32_t off = (uint32_t)(br * 3 + chunk) * 32768 + (uint32_t)bcol * 128
                     + (uint32_t)(((kg ^ (bcol & 7)) * 8 + ki) * 2);
        *(unsigned short*)(g_Wc + off) = __half_as_ushort(val);
        return;
    }
    // ---- quantum setup (block 192, threads 0..31) ----
    __shared__ float sUr[2][DIM][DIM];
    __shared__ float sUi[2][DIM][DIM];
    int t = threadIdx.x;
    if (t < 32) {
        int br  = t >> 4;
        int col = t & 15;
        const float* qw = br ? qw2 : qw1;
        float vr[DIM], vi[DIM];
        #pragma unroll
        for (int k = 0; k < DIM; k++) { vr[k] = (k == col) ? 1.f : 0.f; vi[k] = 0.f; }

        for (int l = 0; l < 2; l++) {
            for (int q = 0; q < NQ; q++) {
                int s = 8 >> q;
                {   // RX
                    float th = qw[(l * NQ + q) * 3 + 0];
                    float c, sn; sincosf(0.5f * th, &sn, &c);
                    #pragma unroll
                    for (int i0 = 0; i0 < DIM; i0++) if (!(i0 & s)) {
                        int i1 = i0 | s;
                        float ar = vr[i0], ai = vi[i0], b_r = vr[i1], b_i = vi[i1];
                        vr[i0] = c * ar + sn * b_i;  vi[i0] = c * ai - sn * b_r;
                        vr[i1] = c * b_r + sn * ai;  vi[i1] = c * b_i - sn * ar;
                    }
                }
                {   // RY
                    float th = qw[(l * NQ + q) * 3 + 1];
                    float c, sn; sincosf(0.5f * th, &sn, &c);
                    #pragma unroll
                    for (int i0 = 0; i0 < DIM; i0++) if (!(i0 & s)) {
                        int i1 = i0 | s;
                        float ar = vr[i0], ai = vi[i0], b_r = vr[i1], b_i = vi[i1];
                        vr[i0] = c * ar - sn * b_r;  vi[i0] = c * ai - sn * b_i;
                        vr[i1] = sn * ar + c * b_r;  vi[i1] = sn * ai + c * b_i;
                    }
                }
                {   // RZ
                    float th = qw[(l * NQ + q) * 3 + 2];
                    float c, sn; sincosf(0.5f * th, &sn, &c);
                    #pragma unroll
                    for (int i0 = 0; i0 < DIM; i0++) {
                        float ar = vr[i0], ai = vi[i0];
                        if (i0 & s) { vr[i0] = c * ar - sn * ai; vi[i0] = c * ai + sn * ar; }
                        else        { vr[i0] = c * ar + sn * ai; vi[i0] = c * ai - sn * ar; }
                    }
                }
            }
            const int scs[4] = {8, 4, 2, 1};
            const int sts[4] = {4, 2, 1, 8};
            #pragma unroll
            for (int p = 0; p < 4; p++) {
                int sc = scs[p], st = sts[p];
                #pragma unroll
                for (int i0 = 0; i0 < DIM; i0++)
                    if ((i0 & sc) && !(i0 & st)) {
                        int i1 = i0 | st;
                        float tr = vr[i0], ti = vi[i0];
                        vr[i0] = vr[i1]; vi[i0] = vi[i1];
                        vr[i1] = tr;     vi[i1] = ti;
                    }
            }
        }
        #pragma unroll
        for (int k = 0; k < DIM; k++) { sUr[br][k][col] = vr[k]; sUi[br][k][col] = vi[k]; }
    }
    __syncthreads();
    if (t < 32) {
        int br = t >> 4;
        int i  = t & 15;
        float pw = br ? pw2[0] : pw1[0];
        for (int j = 0; j < DIM; j++) {
            float acc = 0.f;
            #pragma unroll
            for (int k = 0; k < DIM; k++) {
                float d = (k < 8) ? 1.f : -1.f;
                acc += d * (sUr[br][k][i] * sUr[br][k][j] + sUi[br][k][i] * sUi[br][k][j]);
            }
            g_M[br][i][j] = acc * pw;
        }
    }
}

// ---------------------------------------------------------------------------
// Main HMMA kernel (fp16 single-product). CTA: 256 thr = 8 warps
// (wm = wid&1 -> 32 rows, wn = wid>>1 -> 64 cols). CTA: M=64 x N=256, one
// branch. K=192 (padded) in three 64-k chunks, double-buffered cp.async.
// 2 CTAs/SM.
// smem map (bytes):
//   [0, 25600)        X tile: 64 rows x pitch 400B (fp16, k 0..191, 384B used)
//   [25600, 91136)    W double buffer: 2 x 256 cols x 128B (swizzled)
// epilogue overlay in X region: ps @0 (4KB), sW2 @4096 (4KB), sB1 @8192 (1KB)
// ---------------------------------------------------------------------------
#define XOFF  0u
#define XPITCH 400u
#define WOFF  25600u
#define SMEM_BYTES 91136

__global__ __launch_bounds__(256, 2)
void qc_hmma_kernel(const float* __restrict__ state, const float* __restrict__ action,
                    const float* __restrict__ b11, const float* __restrict__ b12,
                    const float* __restrict__ W21, const float* __restrict__ W22,
                    const float* __restrict__ b21, const float* __restrict__ b22,
                    const float* __restrict__ pb1, const float* __restrict__ pb2,
                    float* __restrict__ out, int B) {
    extern __shared__ char smem[];
    uint32_t sb = smem_u32(smem);
    int t = threadIdx.x, lane = t & 31, wid = t >> 5;
    int wm = wid & 1, wn = wid >> 1;           // wn in 0..3
    int mtile = blockIdx.x >> 1, br = blockIdx.x & 1;
    int row0 = mtile * 64;
    const unsigned char* wsrc = g_Wc + (size_t)br * 3 * 32768;

    // prefetch W chunk 0 (fully coalesced: contiguous 16B per lane)
    #pragma unroll
    for (int i = 0; i < 8; i++)
        cp_async16(sb + WOFF + (uint32_t)(t * 16 + i * 4096), wsrc + t * 16 + i * 4096);
    asm volatile("cp.async.commit_group;" ::: "memory");

    // X tile: load fp32, convert fp16, store (1280 tasks of 8 elems)
    #pragma unroll
    for (int p = 0; p < 5; p++) {
        int task = t + p * 256;
        int r = task / 20, g = task - r * 20;
        const float* src = (g < 16) ? state + (size_t)(row0 + r) * 128 + g * 8
                                    : action + (size_t)(row0 + r) * 32 + (g - 16) * 8;
        float4 va = *(const float4*)src;
        float4 vb = *(const float4*)(src + 4);
        uint32_t hp[4];
        hp[0] = (uint32_t)__half_as_ushort(__float2half_rn(va.x))
              | ((uint32_t)__half_as_ushort(__float2half_rn(va.y)) << 16);
        hp[1] = (uint32_t)__half_as_ushort(__float2half_rn(va.z))
              | ((uint32_t)__half_as_ushort(__float2half_rn(va.w)) << 16);
        hp[2] = (uint32_t)__half_as_ushort(__float2half_rn(vb.x))
              | ((uint32_t)__half_as_ushort(__float2half_rn(vb.y)) << 16);
        hp[3] = (uint32_t)__half_as_ushort(__float2half_rn(vb.z))
              | ((uint32_t)__half_as_ushort(__float2half_rn(vb.w)) << 16);
        uint32_t base = sb + XOFF + (uint32_t)(r * XPITCH + g * 16);
        asm volatile("st.shared.v4.b32 [%0], {%1,%2,%3,%4};"
                     :: "r"(base), "r"(hp[0]), "r"(hp[1]), "r"(hp[2]), "r"(hp[3]) : "memory");
    }
    // zero-pad k 160..191 (64 rows x 4 groups of 16B)
    {
        int r = t >> 2, g2 = t & 3;
        uint32_t base = sb + XOFF + (uint32_t)(r * XPITCH + 320 + g2 * 16);
        asm volatile("st.shared.v4.b32 [%0], {%1,%1,%1,%1};" :: "r"(base), "r"(0u) : "memory");
    }

    // per-lane ldmatrix bases
    uint32_t a_base = sb + XOFF + (uint32_t)((wm * 32 + (lane & 15)) * XPITCH + (lane >> 4) * 16);
    uint32_t b_base = (uint32_t)((wn * 64 + (lane & 15)) * 128);
    uint32_t ssx = lane & 7, hh = lane >> 4;

    // precomputed B addresses: baddr[buf][ks]
    uint32_t baddr[2][4];
    #pragma unroll
    for (int ks = 0; ks < 4; ks++) {
        uint32_t kgx = (((uint32_t)(ks * 2) + hh) ^ ssx) << 4;
        baddr[0][ks] = sb + WOFF + b_base + kgx;
        baddr[1][ks] = sb + WOFF + 32768u + b_base + kgx;
    }

    float acc[2][8][4];
    #pragma unroll
    for (int m = 0; m < 2; m++)
        #pragma unroll
        for (int n = 0; n < 8; n++)
            #pragma unroll
            for (int j = 0; j < 4; j++) acc[m][n][j] = 0.f;

    #pragma unroll
    for (int c = 0; c < 3; c++) {
        asm volatile("cp.async.wait_group 0;" ::: "memory");
        __syncthreads();
        if (c < 2) {   // prefetch next chunk into other buffer
            const unsigned char* src = wsrc + (size_t)(c + 1) * 32768;
            uint32_t dst = sb + WOFF + (uint32_t)(((c + 1) & 1) * 32768);
            #pragma unroll
            for (int i = 0; i < 8; i++)
                cp_async16(dst + (uint32_t)(t * 16 + i * 4096), src + t * 16 + i * 4096);
            asm volatile("cp.async.commit_group;" ::: "memory");
        }
        const int buf = c & 1;
        #pragma unroll
        for (int ks = 0; ks < 4; ks++) {
            const uint32_t koff = (uint32_t)(c * 128 + ks * 32);
            // --- all fragment loads first (independent issues) ---
            uint32_t a0[4], a1[4], bfr[4][4];
            ldsm4(a0, a_base + koff);
            ldsm4(a1, a_base + 16 * XPITCH + koff);
            ldsm4(bfr[0], baddr[buf][ks]);
            ldsm4(bfr[1], baddr[buf][ks] + 2048);
            ldsm4(bfr[2], baddr[buf][ks] + 4096);
            ldsm4(bfr[3], baddr[buf][ks] + 6144);
            // --- then 16 MMAs ---
            #pragma unroll
            for (int n2 = 0; n2 < 4; n2++) {
                mma16816(acc[0][2 * n2],     a0, bfr[n2][0], bfr[n2][2]);
                mma16816(acc[0][2 * n2 + 1], a0, bfr[n2][1], bfr[n2][3]);
                mma16816(acc[1][2 * n2],     a1, bfr[n2][0], bfr[n2][2]);
                mma16816(acc[1][2 * n2 + 1], a1, bfr[n2][1], bfr[n2][3]);
            }
        }
    }

    // ---------------- epilogue ----------------
    __syncthreads();   // all warps done reading X region
    float* ps  = (float*)(smem + 0);        // [4][64][4]
    float* sW2 = (float*)(smem + 4096);     // [256][4]
    float* sB1 = (float*)(smem + 8192);     // [256]
    {
        int col = t;
        const float* W2 = br ? W22 : W21;
        sW2[col * 4 + 0] = W2[0 * 256 + col];
        sW2[col * 4 + 1] = W2[1 * 256 + col];
        sW2[col * 4 + 2] = W2[2 * 256 + col];
        sW2[col * 4 + 3] = W2[3 * 256 + col];
        sB1[col] = br ? b12[col] : b11[col];
    }
    __syncthreads();

    float p[4][4];
    #pragma unroll
    for (int s = 0; s < 4; s++)
        #pragma unroll
        for (int j = 0; j < 4; j++) p[s][j] = 0.f;

    #pragma unroll
    for (int m = 0; m < 2; m++)
        #pragma unroll
        for (int n = 0; n < 8; n++) {
            int c0 = wn * 64 + n * 8 + 2 * (lane & 3);
            float bb0 = sB1[c0], bb1 = sB1[c0 + 1];
            float h0 = fmaxf(acc[m][n][0] + bb0, 0.f);
            float h1 = fmaxf(acc[m][n][1] + bb1, 0.f);
            float h2 = fmaxf(acc[m][n][2] + bb0, 0.f);
            float h3 = fmaxf(acc[m][n][3] + bb1, 0.f);
            const float4 w0 = *(const float4*)(sW2 + c0 * 4);
            const float4 w1 = *(const float4*)(sW2 + (c0 + 1) * 4);
            p[2*m][0] = fmaf(w0.x, h0, fmaf(w1.x, h1, p[2*m][0]));
            p[2*m][1] = fmaf(w0.y, h0, fmaf(w1.y, h1, p[2*m][1]));
            p[2*m][2] = fmaf(w0.z, h0, fmaf(w1.z, h1, p[2*m][2]));
            p[2*m][3] = fmaf(w0.w, h0, fmaf(w1.w, h1, p[2*m][3]));
            p[2*m+1][0] = fmaf(w0.x, h2, fmaf(w1.x, h3, p[2*m+1][0]));
            p[2*m+1][1] = fmaf(w0.y, h2, fmaf(w1.y, h3, p[2*m+1][1]));
            p[2*m+1][2] = fmaf(w0.z, h2, fmaf(w1.z, h3, p[2*m+1][2]));
            p[2*m+1][3] = fmaf(w0.w, h2, fmaf(w1.w, h3, p[2*m+1][3]));
        }
    #pragma unroll
    for (int off = 1; off < 4; off <<= 1)
        #pragma unroll
        for (int s = 0; s < 4; s++)
            #pragma unroll
            for (int j = 0; j < 4; j++)
                p[s][j] += __shfl_xor_sync(0xffffffffu, p[s][j], off);

    if ((lane & 3) == 0) {
        int rq = lane >> 2;
        #pragma unroll
        for (int s = 0; s < 4; s++) {
            int row = wm * 32 + (s >> 1) * 16 + (s & 1) * 8 + rq;
            *(float4*)(ps + ((size_t)wn * 64 + row) * 4) =
                make_float4(p[s][0], p[s][1], p[s][2], p[s][3]);
        }
    }
    __syncthreads();

    if (t < 64) {
        int row = t;
        const float4* psv = (const float4*)ps;
        float4 s0 = psv[0 * 64 + row];
        float4 s1 = psv[1 * 64 + row];
        float4 s2 = psv[2 * 64 + row];
        float4 s3 = psv[3 * 64 + row];
        const float* b2 = br ? b22 : b21;
        float q0 = s0.x + s1.x + s2.x + s3.x + __ldg(b2 + 0);
        float q1 = s0.y + s1.y + s2.y + s3.y + __ldg(b2 + 1);
        float q2 = s0.z + s1.z + s2.z + s3.z + __ldg(b2 + 2);
        float q3 = s0.w + s1.w + s2.w + s3.w + __ldg(b2 + 3);

        float cc4[4], ss4[4];
        sincosf(0.5f * q0, &ss4[0], &cc4[0]);
        sincosf(0.5f * q1, &ss4[1], &cc4[1]);
        sincosf(0.5f * q2, &ss4[2], &cc4[2]);
        sincosf(0.5f * q3, &ss4[3], &cc4[3]);
        float a[16];
        #pragma unroll
        for (int idx = 0; idx < 16; idx++) {
            float v = ((idx >> 3) & 1) ? ss4[0] : cc4[0];
            v *= ((idx >> 2) & 1) ? ss4[1] : cc4[1];
            v *= ((idx >> 1) & 1) ? ss4[2] : cc4[2];
            v *= (idx & 1) ? ss4[3] : cc4[3];
            a[idx] = v;
        }
        const float* M = &g_M[br][0][0];
        float qo = 0.f;
        #pragma unroll
        for (int i2 = 0; i2 < 16; i2++) {
            float mi = 0.f;
            #pragma unroll
            for (int j = 0; j < 16; j++) mi = fmaf(M[i2 * 16 + j], a[j], mi);
            qo = fmaf(a[i2], mi, qo);
        }
        out[(size_t)br * B + row0 + row] = qo + (br ? __ldg(pb2) : __ldg(pb1));
    }
}

// ---------------------------------------------------------------------------
// Launch
// ---------------------------------------------------------------------------
extern "C" void kernel_launch(void* const* d_in, const int* in_sizes, int n_in,
                              void* d_out, int out_size) {
    const float* state  = (const float*)d_in[0];
    const float* action = (const float*)d_in[1];
    const float* q1_W1  = (const float*)d_in[2];
    const float* q1_b1  = (const float*)d_in[3];
    const float* q1_W2  = (const float*)d_in[4];
    const float* q1_b2  = (const float*)d_in[5];
    const float* q2_W1  = (const float*)d_in[6];
    const float* q2_b1  = (const float*)d_in[7];
    const float* q2_W2  = (const float*)d_in[8];
    const float* q2_b2  = (const float*)d_in[9];
    const float* q1_qw  = (const float*)d_in[10];
    const float* q2_qw  = (const float*)d_in[11];
    const float* q1_pw  = (const float*)d_in[12];
    const float* q1_pb  = (const float*)d_in[13];
    const float* q2_pw  = (const float*)d_in[14];
    const float* q2_pb  = (const float*)d_in[15];
    float* out = (float*)d_out;

    int B = in_sizes[0] / 128;

    cudaFuncSetAttribute(qc_hmma_kernel,
                         cudaFuncAttributeMaxDynamicSharedMemorySize, SMEM_BYTES);

    qc_prep_kernel<<<193, 512>>>(q1_W1, q2_W1, q1_qw, q2_qw, q1_pw, q2_pw);
    qc_hmma_kernel<<<(B / 64) * 2, 256, SMEM_BYTES>>>(
        state, action, q1_b1, q2_b1, q1_W2, q2_W2, q1_b2, q2_b2,
        q1_pb, q2_pb, out, B);
}